// round 8
// baseline (speedup 1.0000x reference)
#include <cuda_runtime.h>
#include <cuda_fp16.h>
#include <cstdint>
#include <math.h>

// ---------------- problem constants ----------------
#define NUM_E 1024
#define DIM   64
#define TT    2048
#define BB    32
#define NROWS (BB * TT)          // 65536
#define NELEM (BB * DIM * TT)    // 4194304

// output layout (flattened tuple, fp32)
#define COMMIT_OFF 4194304
#define PERP_OFF   4194305
#define AVG_OFF    4194306
#define IDX_OFF    4195330
#define USAGE_OFF  4260866

// ---------------- tiling ----------------
#define ROWS_CTA 64                  // rows per CTA (4 m-tiles)
#define NCH      8                   // code chunks of 128
#define CHB2     16384               // packed B chunk (split0): 4 pkt * 16 nt * 32 * 8B

// smem offsets (main kernel)
#define SA_OFF   0                   // A frags: 4 mt * 4 pkt * 32 * 16B = 8KB
#define SB_OFF   8192                // B frags: 8 * 16KB = 128KB
#define SE2_OFF  139264              // 4KB
#define SXN_OFF  143360              // 64 * 4  ||x||
#define SRN_OFF  143616              // 64 * 4  ||xi||
#define SB1_OFF  143872              // 64*8*4
#define SI1_OFF  145920              // 64*8*4
#define SB2_OFF  147968              // 64*8*4
#define SMEM_DYN 150528

// ---------------- device scratch ----------------
__device__ __align__(16) unsigned char g_Bp[NCH * CHB2];  // packed B frags (split0)
__device__ float g_e2[NUM_E];
__device__ float g_hm2[32];    // per-prep-block max ||eta||^2
__device__ float g_e0m2[32];   // per-prep-block max ||e0||^2
__device__ int   g_idx[NROWS];
__device__ int   g_list[NROWS];
__device__ int   g_cnt;
__device__ int   g_counts[NUM_E];
__device__ float g_sumsq;

// ---------------- helpers ----------------
__device__ __forceinline__ uint32_t smem_u32(const void* p) {
    uint32_t a;
    asm("{ .reg .u64 t; cvta.to.shared.u64 t, %1; cvt.u32.u64 %0, t; }" : "=r"(a) : "l"(p));
    return a;
}
__device__ __forceinline__ void cp16(uint32_t saddr, const void* g) {
    asm volatile("cp.async.cg.shared.global [%0], [%1], 16;" :: "r"(saddr), "l"(g));
}
__device__ __forceinline__ void mma16816(float* d, const uint4 a, const uint2 b) {
    asm volatile(
        "mma.sync.aligned.m16n8k16.row.col.f32.f16.f16.f32 "
        "{%0,%1,%2,%3}, {%4,%5,%6,%7}, {%8,%9}, {%0,%1,%2,%3};"
        : "+f"(d[0]), "+f"(d[1]), "+f"(d[2]), "+f"(d[3])
        : "r"(a.x), "r"(a.y), "r"(a.z), "r"(a.w), "r"(b.x), "r"(b.y));
}

// ---------------- prep: pack split0 frags + norms + error maxima + zero scratch ----------------
// 32 blocks x 32 threads, one code per thread
__global__ void prep_kernel(const float* __restrict__ embed) {
    const int c = blockIdx.x * 32 + threadIdx.x;
    const float* e = embed + (size_t)c * DIM;
    uint32_t h0[32];
    float e2 = 0.f, e02 = 0.f, res2 = 0.f;
#pragma unroll 8
    for (int j = 0; j < 32; ++j) {
        float2 v = *(const float2*)(e + 2 * j);
        e2 += v.x * v.x + v.y * v.y;
        __half a = __float2half_rn(v.x), b = __float2half_rn(v.y);
        float fa = __half2float(a), fb = __half2float(b);
        e02 += fa * fa + fb * fb;
        float rx = v.x - fa, ry = v.y - fb;
        res2 += rx * rx + ry * ry;
        h0[j] = (uint32_t)__half_as_ushort(a) | ((uint32_t)__half_as_ushort(b) << 16);
    }
    g_e2[c] = e2;
    g_counts[c] = 0;
    if (c == 0) { g_sumsq = 0.f; g_cnt = 0; }

    const int chunk = c >> 7, n_in = c & 127, nt = n_in >> 3, lq = n_in & 7;
    uint32_t* dstb = (uint32_t*)(g_Bp + (size_t)chunk * CHB2);
#pragma unroll
    for (int pkt = 0; pkt < 4; ++pkt) {
#pragma unroll
        for (int cc = 0; cc < 4; ++cc) {
            uint32_t* d = dstb + (((pkt * 16 + nt) * 32) + 4 * lq + cc) * 2;
            d[0] = h0[pkt * 8 + cc];
            d[1] = h0[pkt * 8 + 4 + cc];
        }
    }
    // warp max reduce of res2 / e02
#pragma unroll
    for (int o = 16; o; o >>= 1) {
        res2 = fmaxf(res2, __shfl_xor_sync(0xffffffffu, res2, o));
        e02  = fmaxf(e02,  __shfl_xor_sync(0xffffffffu, e02,  o));
    }
    if (threadIdx.x == 0) { g_hm2[blockIdx.x] = res2; g_e0m2[blockIdx.x] = e02; }
}

// ---------------- main: 1-product HMMA GEMM + top-2 + sound flag ----------------
// 512 threads = 16 warps = 2 row-groups x 8 code-groups; 64 rows/CTA
__global__ void __launch_bounds__(512, 1)
vq_mma_kernel(const float* __restrict__ x, float* __restrict__ out_idxf) {
    extern __shared__ char sm[];
    uint32_t* sA  = (uint32_t*)(sm + SA_OFF);
    float*    sE2 = (float*)(sm + SE2_OFF);
    float*    sXn = (float*)(sm + SXN_OFF);
    float*    sRn = (float*)(sm + SRN_OFF);
    float*    sB1 = (float*)(sm + SB1_OFF);
    int*      sI1 = (int*)(sm + SI1_OFF);
    float*    sB2 = (float*)(sm + SB2_OFF);
    const uint32_t sBaddr = smem_u32(sm + SB_OFF);

    const int tid = threadIdx.x, lane = tid & 31, w = tid >> 5;
    const int rg = w >> 3, cg = w & 7;   // 2 row-groups x 8 code-groups

    // load ALL of B (128KB) once
    for (int k = tid; k < (NCH * CHB2) / 16; k += 512)
        cp16(sBaddr + k * 16, (const char*)g_Bp + k * 16);
    asm volatile("cp.async.commit_group;" ::: "memory");

    // build A fragments (split0) + per-row norms; thread = (row, octant)
    {
        const int r = tid >> 3, o = tid & 7;
        const int q = o >> 1, halfq = o & 1;
        const int grow = blockIdx.x * ROWS_CTA + r;
        const float* xp = x + (size_t)(grow >> 11) * (DIM * TT) + (grow & (TT - 1));
        uint32_t h0[4];
        float x2 = 0.f, xi2 = 0.f;
#pragma unroll
        for (int j = 0; j < 4; ++j) {
            float va = xp[(size_t)(8 * o + 2 * j) * TT];
            float vb = xp[(size_t)(8 * o + 2 * j + 1) * TT];
            __half ha = __float2half_rn(va), hb = __float2half_rn(vb);
            float fa = __half2float(ha), fb = __half2float(hb);
            float ra = va - fa, rb = vb - fb;
            x2 += va * va + vb * vb;
            xi2 += ra * ra + rb * rb;
            h0[j] = (uint32_t)__half_as_ushort(ha) | ((uint32_t)__half_as_ushort(hb) << 16);
        }
        // reduce norms over the 8 octant lanes (consecutive lanes in warp)
#pragma unroll
        for (int off = 1; off < 8; off <<= 1) {
            x2  += __shfl_xor_sync(0xffffffffu, x2,  off);
            xi2 += __shfl_xor_sync(0xffffffffu, xi2, off);
        }
        if (o == 0) { sXn[r] = sqrtf(x2); sRn[r] = sqrtf(xi2); }

        const int mt = r >> 4, rr = r & 15;
        const int wsel = ((rr < 8) ? 0 : 1) + (halfq ? 2 : 0);
#pragma unroll
        for (int cc = 0; cc < 4; ++cc)
            sA[(((mt * 4 + q) * 32) + 4 * (rr & 7) + cc) * 4 + wsel] = h0[cc];
        for (int i = tid; i < NUM_E; i += 512) sE2[i] = g_e2[i];
    }
    asm volatile("cp.async.wait_group 0;" ::: "memory");
    __syncthreads();

    // top-2 per row-position, registers only
    float b1_[4] = {3.4e38f, 3.4e38f, 3.4e38f, 3.4e38f};
    float b2_[4] = {3.4e38f, 3.4e38f, 3.4e38f, 3.4e38f};
    int   i1_[4] = {0, 0, 0, 0};

#define UPD(h, s, c) do { \
        if ((s) < b1_[h]) { b2_[h] = b1_[h]; b1_[h] = (s); i1_[h] = (c); } \
        else if ((s) < b2_[h]) b2_[h] = (s); \
    } while (0)

    for (int ch = 0; ch < NCH; ++ch) {
        const uint32_t* Bb = (const uint32_t*)(sm + SB_OFF + ch * CHB2);

        float acc[2][2][4];
#pragma unroll
        for (int m = 0; m < 2; ++m)
#pragma unroll
            for (int n = 0; n < 2; ++n)
#pragma unroll
                for (int j = 0; j < 4; ++j) acc[m][n][j] = 0.f;

#pragma unroll
        for (int kt = 0; kt < 4; ++kt) {
            uint4 Af[2];
#pragma unroll
            for (int m = 0; m < 2; ++m)
                Af[m] = *(const uint4*)(sA + ((((rg * 2 + m) * 4 + kt) * 32) + lane) * 4);
#pragma unroll
            for (int n = 0; n < 2; ++n) {
                uint2 Bf = *(const uint2*)(Bb + (((kt * 16 + cg * 2 + n) * 32) + lane) * 2);
#pragma unroll
                for (int m = 0; m < 2; ++m) mma16816(acc[m][n], Af[m], Bf);
            }
        }

        const int cb = ch * 128 + cg * 16 + 2 * (lane & 3);
#pragma unroll
        for (int n = 0; n < 2; ++n) {
            const int c0 = cb + n * 8;
            const float ea = sE2[c0], eb = sE2[c0 + 1];
#pragma unroll
            for (int m = 0; m < 2; ++m) {
                const int ha = 2 * m, hb = 2 * m + 1;
                float s0 = fmaf(-2.f, acc[m][n][0], ea);
                float s1 = fmaf(-2.f, acc[m][n][1], eb);
                float s2 = fmaf(-2.f, acc[m][n][2], ea);
                float s3 = fmaf(-2.f, acc[m][n][3], eb);
                UPD(ha, s0, c0); UPD(ha, s1, c0 + 1);
                UPD(hb, s2, c0); UPD(hb, s3, c0 + 1);
            }
        }
    }
#undef UPD

    // quad merge of top-2 sets (lanes 4q..4q+3 share rows)
#pragma unroll
    for (int h = 0; h < 4; ++h) {
#pragma unroll
        for (int off = 1; off < 4; off <<= 1) {
            float ob1 = __shfl_xor_sync(0xffffffffu, b1_[h], off);
            int   oi1 = __shfl_xor_sync(0xffffffffu, i1_[h], off);
            float ob2 = __shfl_xor_sync(0xffffffffu, b2_[h], off);
            if (ob1 < b1_[h] || (ob1 == b1_[h] && oi1 < i1_[h])) {
                b2_[h] = fminf(b1_[h], ob2);
                b1_[h] = ob1; i1_[h] = oi1;
            } else {
                b2_[h] = fminf(b2_[h], ob1);
            }
        }
    }
    if ((lane & 3) == 0) {
        const int q = lane >> 2;
#pragma unroll
        for (int h = 0; h < 4; ++h) {
            const int m = h >> 1, hb = h & 1;
            const int row = rg * 32 + m * 16 + hb * 8 + q;
            sB1[row * 8 + cg] = b1_[h];
            sI1[row * 8 + cg] = i1_[h];
            sB2[row * 8 + cg] = b2_[h];
        }
    }
    __syncthreads();

    if (tid < ROWS_CTA) {
        float B1 = sB1[tid * 8], B2 = sB2[tid * 8];
        int   I1 = sI1[tid * 8];
#pragma unroll
        for (int g = 1; g < 8; ++g) {
            float ob1 = sB1[tid * 8 + g], ob2 = sB2[tid * 8 + g];
            int   oi1 = sI1[tid * 8 + g];
            if (ob1 < B1 || (ob1 == B1 && oi1 < I1)) {
                B2 = fminf(B1, ob2);
                B1 = ob1; I1 = oi1;
            } else {
                B2 = fminf(B2, ob1);
            }
        }
        // sound window: 2w, w = 2(||x||*HM + ||xi||*E0M) + margin
        float hm2 = g_hm2[0], e0m2 = g_e0m2[0];
#pragma unroll
        for (int i = 1; i < 32; ++i) {
            hm2 = fmaxf(hm2, g_hm2[i]);
            e0m2 = fmaxf(e0m2, g_e0m2[i]);
        }
        const float Wt = 4.0f * (sXn[tid] * sqrtf(hm2) + sRn[tid] * sqrtf(e0m2)) + 6e-3f;
        const int grow = blockIdx.x * ROWS_CTA + tid;
        if (B2 - B1 > Wt) {
            g_idx[grow] = I1;
            out_idxf[grow] = (float)I1;
            atomicAdd(&g_counts[I1], 1);
        } else {
            const int pos = atomicAdd(&g_cnt, 1);
            g_list[pos] = grow;
        }
    }
}

// ---------------- fallback: exact rescore of flagged rows ----------------
__global__ void fallback_kernel(const float* __restrict__ x,
                                const float* __restrict__ embed,
                                float* __restrict__ out_idxf) {
    __shared__ float sx[DIM];
    __shared__ float rb[128];
    __shared__ int   ri[128];
    const int tid = threadIdx.x;
    const int cnt = g_cnt;

    for (int li = blockIdx.x; li < cnt; li += gridDim.x) {
        const int row = g_list[li];
        if (tid < DIM)
            sx[tid] = x[(size_t)(row >> 11) * (DIM * TT) + (size_t)tid * TT + (row & (TT - 1))];
        __syncthreads();

        float best = 3.4e38f;
        int bidx = 0;
        for (int c = tid; c < NUM_E; c += 128) {   // ascending within thread
            const float4* ep = (const float4*)(embed + (size_t)c * DIM);
            float d = 0.f;
#pragma unroll
            for (int j = 0; j < 16; ++j) {
                float4 e = ep[j];
                float d0 = sx[4 * j]     - e.x;
                float d1 = sx[4 * j + 1] - e.y;
                float d2 = sx[4 * j + 2] - e.z;
                float d3 = sx[4 * j + 3] - e.w;
                d += d0 * d0 + d1 * d1 + d2 * d2 + d3 * d3;
            }
            if (d < best) { best = d; bidx = c; }
        }
        rb[tid] = best; ri[tid] = bidx;
        __syncthreads();
        for (int s = 64; s; s >>= 1) {
            if (tid < s) {
                float v = rb[tid + s];
                int   i = ri[tid + s];
                if (v < rb[tid] || (v == rb[tid] && i < ri[tid])) { rb[tid] = v; ri[tid] = i; }
            }
            __syncthreads();
        }
        if (tid == 0) {
            g_idx[row] = ri[0];
            out_idxf[row] = (float)ri[0];
            atomicAdd(&g_counts[ri[0]], 1);
        }
        __syncthreads();
    }
}

// ---------------- gather + straight-through + commitment loss ----------------
__global__ void gather_kernel(const float* __restrict__ x,
                              const float* __restrict__ embed,
                              float* __restrict__ out_q) {
    __shared__ float warpsum[8];
    const int gid = blockIdx.x * blockDim.x + threadIdx.x;
    const int lin = gid * 4;
    const int t_i = lin & (TT - 1);
    const int d_i = (lin >> 11) & (DIM - 1);
    const int b_i = lin >> 17;

    float4 xv = *(const float4*)(x + lin);
    const int rowbase = (b_i << 11) + t_i;
    int4 id = *(const int4*)(g_idx + rowbase);

    float q0 = embed[id.x * DIM + d_i];
    float q1 = embed[id.y * DIM + d_i];
    float q2 = embed[id.z * DIM + d_i];
    float q3 = embed[id.w * DIM + d_i];

    float d0 = q0 - xv.x, d1 = q1 - xv.y, d2 = q2 - xv.z, d3 = q3 - xv.w;
    float4 ov = make_float4(xv.x + d0, xv.y + d1, xv.z + d2, xv.w + d3);
    *(float4*)(out_q + lin) = ov;

    float s = d0 * d0 + d1 * d1 + d2 * d2 + d3 * d3;
#pragma unroll
    for (int o = 16; o; o >>= 1) s += __shfl_down_sync(0xffffffffu, s, o);
    const int lane = threadIdx.x & 31, w = threadIdx.x >> 5;
    if (lane == 0) warpsum[w] = s;
    __syncthreads();
    if (w == 0) {
        float v = lane < 8 ? warpsum[lane] : 0.f;
#pragma unroll
        for (int o = 4; o; o >>= 1) v += __shfl_down_sync(0xffffffffu, v, o);
        if (lane == 0) atomicAdd(&g_sumsq, v);
    }
}

// ---------------- finalize ----------------
__global__ void finalize_kernel(float* __restrict__ out) {
    __shared__ float s1[32], s2[32];
    const int tid = threadIdx.x;
    float p = (float)g_counts[tid] * (1.0f / (float)NROWS);
    out[AVG_OFF + tid] = p;
    float t1 = p * logf(p + 1e-10f);
    float t2 = p * logf(p * (float)NUM_E + 1e-10f);
#pragma unroll
    for (int o = 16; o; o >>= 1) {
        t1 += __shfl_down_sync(0xffffffffu, t1, o);
        t2 += __shfl_down_sync(0xffffffffu, t2, o);
    }
    const int lane = tid & 31, w = tid >> 5;
    if (lane == 0) { s1[w] = t1; s2[w] = t2; }
    __syncthreads();
    if (w == 0) {
        float a = s1[lane], b = s2[lane];
#pragma unroll
        for (int o = 16; o; o >>= 1) {
            a += __shfl_down_sync(0xffffffffu, a, o);
            b += __shfl_down_sync(0xffffffffu, b, o);
        }
        if (lane == 0) {
            out[PERP_OFF]   = expf(-a);
            out[USAGE_OFF]  = b;
            out[COMMIT_OFF] = 0.25f * g_sumsq / (float)NELEM;
        }
    }
}

extern "C" void kernel_launch(void* const* d_in, const int* in_sizes, int n_in,
                              void* d_out, int out_size) {
    const float* x     = (const float*)d_in[0];
    const float* embed = (const float*)d_in[1];
    float* out = (float*)d_out;

    cudaFuncSetAttribute(vq_mma_kernel, cudaFuncAttributeMaxDynamicSharedMemorySize, SMEM_DYN);

    prep_kernel<<<32, 32>>>(embed);
    vq_mma_kernel<<<NROWS / ROWS_CTA, 512, SMEM_DYN>>>(x, out + IDX_OFF);
    fallback_kernel<<<296, 128>>>(x, embed, out + IDX_OFF);
    gather_kernel<<<NELEM / (256 * 4), 256>>>(x, embed, out);
    finalize_kernel<<<1, 1024>>>(out);
}

// round 9
// speedup vs baseline: 2.1774x; 2.1774x over previous
#include <cuda_runtime.h>
#include <cuda_fp16.h>
#include <cstdint>
#include <math.h>

// ---------------- problem constants ----------------
#define NUM_E 1024
#define DIM   64
#define TT    2048
#define BB    32
#define NROWS (BB * TT)          // 65536
#define NELEM (BB * DIM * TT)    // 4194304

// output layout (flattened tuple, fp32)
#define COMMIT_OFF 4194304
#define PERP_OFF   4194305
#define AVG_OFF    4194306
#define IDX_OFF    4195330
#define USAGE_OFF  4260866

// ---------------- tiling ----------------
#define ROWS_CTA 64                  // rows per CTA (4 m-tiles)
#define NCH      8                   // code chunks of 128
#define CHB      32768               // full 2-split packed chunk (8 pkt)
#define CHB2     16384               // split0 half (4 pkt)
#define INV2048  4.8828125e-4f

// ---- main kernel smem ----
#define SA_OFF   0                   // A frags split0: 4 mt * 4 pkt * 32 * 16B = 8KB
#define SB_OFF   8192                // B split0 frags: 8 * 16KB = 128KB
#define SE2_OFF  139264              // 4KB
#define SXN_OFF  143360
#define SRN_OFF  143616
#define SB1_OFF  143872
#define SI1_OFF  145920
#define SB2_OFF  147968
#define SMEM_MAIN 150528

// ---- pass2 kernel smem ----
#define P2_SA    0                   // A frags 2-split: 4 mt * 8 pkt * 32*16B = 16KB
#define P2_SB    16384               // 2 * 32KB
#define P2_SE2   81920               // 4KB
#define P2_SRF   86016               // 64*8*4
#define P2_SRI   88064               // 64*8*4
#define P2_SL    90112               // 64*4
#define SMEM_P2  90368

// ---------------- device scratch ----------------
__device__ __align__(16) unsigned char g_Bp[NCH * CHB];  // 2-split packed B
__device__ float g_e2[NUM_E];
__device__ float g_hm2[32];
__device__ float g_e0m2[32];
__device__ int   g_idx[NROWS];
__device__ int   g_list[NROWS];
__device__ int   g_cnt;
__device__ int   g_gdone;
__device__ int   g_counts[NUM_E];
__device__ float g_sumsq;

// ---------------- helpers ----------------
__device__ __forceinline__ uint32_t smem_u32(const void* p) {
    uint32_t a;
    asm("{ .reg .u64 t; cvta.to.shared.u64 t, %1; cvt.u32.u64 %0, t; }" : "=r"(a) : "l"(p));
    return a;
}
__device__ __forceinline__ void cp16(uint32_t saddr, const void* g) {
    asm volatile("cp.async.cg.shared.global [%0], [%1], 16;" :: "r"(saddr), "l"(g));
}
__device__ __forceinline__ void cp_commit() {
    asm volatile("cp.async.commit_group;" ::: "memory");
}
__device__ __forceinline__ void mma16816(float* d, const uint4 a, const uint2 b) {
    asm volatile(
        "mma.sync.aligned.m16n8k16.row.col.f32.f16.f16.f32 "
        "{%0,%1,%2,%3}, {%4,%5,%6,%7}, {%8,%9}, {%0,%1,%2,%3};"
        : "+f"(d[0]), "+f"(d[1]), "+f"(d[2]), "+f"(d[3])
        : "r"(a.x), "r"(a.y), "r"(a.z), "r"(a.w), "r"(b.x), "r"(b.y));
}
__device__ __forceinline__ void split2(float v, uint32_t& u0, uint32_t& u1) {
    __half h0 = __float2half_rn(v);
    float f0 = __half2float(h0);
    __half h1 = __float2half_rn((v - f0) * 2048.0f);
    u0 = (uint32_t)__half_as_ushort(h0);
    u1 = (uint32_t)__half_as_ushort(h1);
}

// ---------------- prep: pack 2-split B frags + norms + maxima + zero scratch ----------------
__global__ void prep_kernel(const float* __restrict__ embed) {
    const int c = blockIdx.x * 32 + threadIdx.x;
    const float* e = embed + (size_t)c * DIM;
    uint32_t h0[32], h1[32];
    float e2 = 0.f, e02 = 0.f, res2 = 0.f;
#pragma unroll 8
    for (int j = 0; j < 32; ++j) {
        float2 v = *(const float2*)(e + 2 * j);
        e2 += v.x * v.x + v.y * v.y;
        uint32_t a0, a1, b0, b1;
        split2(v.x, a0, a1);
        split2(v.y, b0, b1);
        __half ha = __ushort_as_half((unsigned short)a0);
        __half hb = __ushort_as_half((unsigned short)b0);
        float fa = __half2float(ha), fb = __half2float(hb);
        e02 += fa * fa + fb * fb;
        float rx = v.x - fa, ry = v.y - fb;
        res2 += rx * rx + ry * ry;
        h0[j] = a0 | (b0 << 16);
        h1[j] = a1 | (b1 << 16);
    }
    g_e2[c] = e2;
    g_counts[c] = 0;
    if (c == 0) { g_sumsq = 0.f; g_cnt = 0; g_gdone = 0; }

    const int chunk = c >> 7, n_in = c & 127, nt = n_in >> 3, lq = n_in & 7;
    uint32_t* dstb = (uint32_t*)(g_Bp + (size_t)chunk * CHB);
#pragma unroll
    for (int pkt = 0; pkt < 8; ++pkt) {
        const uint32_t* hp = (pkt < 4) ? h0 : h1;
        const int kb = (pkt & 3) * 8;
#pragma unroll
        for (int cc = 0; cc < 4; ++cc) {
            uint32_t* d = dstb + (((pkt * 16 + nt) * 32) + 4 * lq + cc) * 2;
            d[0] = hp[kb + cc];
            d[1] = hp[kb + 4 + cc];
        }
    }
#pragma unroll
    for (int o = 16; o; o >>= 1) {
        res2 = fmaxf(res2, __shfl_xor_sync(0xffffffffu, res2, o));
        e02  = fmaxf(e02,  __shfl_xor_sync(0xffffffffu, e02,  o));
    }
    if (threadIdx.x == 0) { g_hm2[blockIdx.x] = res2; g_e0m2[blockIdx.x] = e02; }
}

// ---------------- main: 1-product HMMA + top-2 + sound flag ----------------
__global__ void __launch_bounds__(512, 1)
vq_mma_kernel(const float* __restrict__ x, float* __restrict__ out_idxf) {
    extern __shared__ char sm[];
    uint32_t* sA  = (uint32_t*)(sm + SA_OFF);
    float*    sE2 = (float*)(sm + SE2_OFF);
    float*    sXn = (float*)(sm + SXN_OFF);
    float*    sRn = (float*)(sm + SRN_OFF);
    float*    sB1 = (float*)(sm + SB1_OFF);
    int*      sI1 = (int*)(sm + SI1_OFF);
    float*    sB2 = (float*)(sm + SB2_OFF);
    const uint32_t sBaddr = smem_u32(sm + SB_OFF);

    const int tid = threadIdx.x, lane = tid & 31, w = tid >> 5;
    const int rg = w >> 3, cg = w & 7;

    // load split0 halves of all 8 chunks (128KB total)
    for (int k = tid; k < 8192; k += 512) {
        const int chk = k >> 10, off = k & 1023;
        cp16(sBaddr + k * 16, (const char*)g_Bp + (size_t)chk * CHB + off * 16);
    }
    cp_commit();

    // A fragments (split0) + per-row norms; thread = (row, octant)
    {
        const int r = tid >> 3, o = tid & 7;
        const int q = o >> 1, halfq = o & 1;
        const int grow = blockIdx.x * ROWS_CTA + r;
        const float* xp = x + (size_t)(grow >> 11) * (DIM * TT) + (grow & (TT - 1));
        uint32_t h0[4];
        float x2 = 0.f, xi2 = 0.f;
#pragma unroll
        for (int j = 0; j < 4; ++j) {
            float va = xp[(size_t)(8 * o + 2 * j) * TT];
            float vb = xp[(size_t)(8 * o + 2 * j + 1) * TT];
            __half ha = __float2half_rn(va), hb = __float2half_rn(vb);
            float fa = __half2float(ha), fb = __half2float(hb);
            float ra = va - fa, rb = vb - fb;
            x2 += va * va + vb * vb;
            xi2 += ra * ra + rb * rb;
            h0[j] = (uint32_t)__half_as_ushort(ha) | ((uint32_t)__half_as_ushort(hb) << 16);
        }
#pragma unroll
        for (int off = 1; off < 8; off <<= 1) {
            x2  += __shfl_xor_sync(0xffffffffu, x2,  off);
            xi2 += __shfl_xor_sync(0xffffffffu, xi2, off);
        }
        if (o == 0) { sXn[r] = sqrtf(x2); sRn[r] = sqrtf(xi2); }

        const int mt = r >> 4, rr = r & 15;
        const int wsel = ((rr < 8) ? 0 : 1) + (halfq ? 2 : 0);
#pragma unroll
        for (int cc = 0; cc < 4; ++cc)
            sA[(((mt * 4 + q) * 32) + 4 * (rr & 7) + cc) * 4 + wsel] = h0[cc];
        for (int i = tid; i < NUM_E; i += 512) sE2[i] = g_e2[i];
    }
    asm volatile("cp.async.wait_group 0;" ::: "memory");
    __syncthreads();

    float b1_[4] = {3.4e38f, 3.4e38f, 3.4e38f, 3.4e38f};
    float b2_[4] = {3.4e38f, 3.4e38f, 3.4e38f, 3.4e38f};
    int   i1_[4] = {0, 0, 0, 0};

#define UPD(h, s, c) do { \
        if ((s) < b1_[h]) { b2_[h] = b1_[h]; b1_[h] = (s); i1_[h] = (c); } \
        else if ((s) < b2_[h]) b2_[h] = (s); \
    } while (0)

    for (int ch = 0; ch < NCH; ++ch) {
        const uint32_t* Bb = (const uint32_t*)(sm + SB_OFF + ch * CHB2);
        float acc[2][2][4];
#pragma unroll
        for (int m = 0; m < 2; ++m)
#pragma unroll
            for (int n = 0; n < 2; ++n)
#pragma unroll
                for (int j = 0; j < 4; ++j) acc[m][n][j] = 0.f;
#pragma unroll
        for (int kt = 0; kt < 4; ++kt) {
            uint4 Af[2];
#pragma unroll
            for (int m = 0; m < 2; ++m)
                Af[m] = *(const uint4*)(sA + ((((rg * 2 + m) * 4 + kt) * 32) + lane) * 4);
#pragma unroll
            for (int n = 0; n < 2; ++n) {
                uint2 Bf = *(const uint2*)(Bb + (((kt * 16 + cg * 2 + n) * 32) + lane) * 2);
#pragma unroll
                for (int m = 0; m < 2; ++m) mma16816(acc[m][n], Af[m], Bf);
            }
        }
        const int cb = ch * 128 + cg * 16 + 2 * (lane & 3);
#pragma unroll
        for (int n = 0; n < 2; ++n) {
            const int c0 = cb + n * 8;
            const float ea = sE2[c0], eb = sE2[c0 + 1];
#pragma unroll
            for (int m = 0; m < 2; ++m) {
                const int ha = 2 * m, hb = 2 * m + 1;
                float s0 = fmaf(-2.f, acc[m][n][0], ea);
                float s1 = fmaf(-2.f, acc[m][n][1], eb);
                float s2 = fmaf(-2.f, acc[m][n][2], ea);
                float s3 = fmaf(-2.f, acc[m][n][3], eb);
                UPD(ha, s0, c0); UPD(ha, s1, c0 + 1);
                UPD(hb, s2, c0); UPD(hb, s3, c0 + 1);
            }
        }
    }
#undef UPD

#pragma unroll
    for (int h = 0; h < 4; ++h) {
#pragma unroll
        for (int off = 1; off < 4; off <<= 1) {
            float ob1 = __shfl_xor_sync(0xffffffffu, b1_[h], off);
            int   oi1 = __shfl_xor_sync(0xffffffffu, i1_[h], off);
            float ob2 = __shfl_xor_sync(0xffffffffu, b2_[h], off);
            if (ob1 < b1_[h] || (ob1 == b1_[h] && oi1 < i1_[h])) {
                b2_[h] = fminf(b1_[h], ob2);
                b1_[h] = ob1; i1_[h] = oi1;
            } else {
                b2_[h] = fminf(b2_[h], ob1);
            }
        }
    }
    if ((lane & 3) == 0) {
        const int q = lane >> 2;
#pragma unroll
        for (int h = 0; h < 4; ++h) {
            const int m = h >> 1, hb = h & 1;
            const int row = rg * 32 + m * 16 + hb * 8 + q;
            sB1[row * 8 + cg] = b1_[h];
            sI1[row * 8 + cg] = i1_[h];
            sB2[row * 8 + cg] = b2_[h];
        }
    }
    __syncthreads();

    if (tid < ROWS_CTA) {
        float B1 = sB1[tid * 8], B2 = sB2[tid * 8];
        int   I1 = sI1[tid * 8];
#pragma unroll
        for (int g = 1; g < 8; ++g) {
            float ob1 = sB1[tid * 8 + g], ob2 = sB2[tid * 8 + g];
            int   oi1 = sI1[tid * 8 + g];
            if (ob1 < B1 || (ob1 == B1 && oi1 < I1)) {
                B2 = fminf(B1, ob2);
                B1 = ob1; I1 = oi1;
            } else {
                B2 = fminf(B2, ob1);
            }
        }
        float hm2 = g_hm2[0], e0m2 = g_e0m2[0];
#pragma unroll
        for (int i = 1; i < 32; ++i) {
            hm2 = fmaxf(hm2, g_hm2[i]);
            e0m2 = fmaxf(e0m2, g_e0m2[i]);
        }
        const float Wt = 4.0f * (sXn[tid] * sqrtf(hm2) + sRn[tid] * sqrtf(e0m2)) + 0.02f;
        const int grow = blockIdx.x * ROWS_CTA + tid;
        if (B2 - B1 > Wt) {
            g_idx[grow] = I1;
            out_idxf[grow] = (float)I1;
            atomicAdd(&g_counts[I1], 1);
        } else {
            const int pos = atomicAdd(&g_cnt, 1);
            g_list[pos] = grow;
        }
    }
}

// ---------------- pass2: exact 2-split HMMA rescore of flagged rows ----------------
__global__ void __launch_bounds__(512, 2)
pass2_kernel(const float* __restrict__ x, float* __restrict__ out_idxf) {
    extern __shared__ char sm[];
    uint32_t* sA  = (uint32_t*)(sm + P2_SA);
    float*    sE2 = (float*)(sm + P2_SE2);
    float*    sRF = (float*)(sm + P2_SRF);
    int*      sRI = (int*)(sm + P2_SRI);
    int*      sL  = (int*)(sm + P2_SL);
    const uint32_t sBaddr = smem_u32(sm + P2_SB);

    const int tid = threadIdx.x, lane = tid & 31, w = tid >> 5;
    const int rg = w >> 3, cg = w & 7;
    const int cnt = g_cnt;

    for (int i = tid; i < NUM_E; i += 512) sE2[i] = g_e2[i];

    const int PA_[12]  = {0,1,2,3, 0,1,2,3, 4,5,6,7};   // unused placeholder (kept for clarity)
    (void)PA_;

    for (int tile = blockIdx.x; tile * ROWS_CTA < cnt; tile += gridDim.x) {
        if (tid < ROWS_CTA) {
            const int p = tile * ROWS_CTA + tid;
            sL[tid] = (p < cnt) ? g_list[p] : -1;
        }
        __syncthreads();

        // prefetch B chunks 0,1 (full 2-split)
        for (int k = tid; k < CHB / 16; k += 512)
            cp16(sBaddr + k * 16, (const char*)g_Bp + k * 16);
        cp_commit();
        for (int k = tid; k < CHB / 16; k += 512)
            cp16(sBaddr + CHB + k * 16, (const char*)g_Bp + CHB + k * 16);
        cp_commit();

        // A build (2-split), indirect rows
        {
            const int r = tid >> 3, o = tid & 7;
            const int q = o >> 1, halfq = o & 1;
            int grow = sL[r];
            if (grow < 0) grow = 0;
            const float* xp = x + (size_t)(grow >> 11) * (DIM * TT) + (grow & (TT - 1));
            uint32_t h0[4], h1[4];
#pragma unroll
            for (int j = 0; j < 4; ++j) {
                float va = xp[(size_t)(8 * o + 2 * j) * TT];
                float vb = xp[(size_t)(8 * o + 2 * j + 1) * TT];
                uint32_t a0, a1, b0, b1;
                split2(va, a0, a1);
                split2(vb, b0, b1);
                h0[j] = a0 | (b0 << 16);
                h1[j] = a1 | (b1 << 16);
            }
            const int mt = r >> 4, rr = r & 15;
            const int wsel = ((rr < 8) ? 0 : 1) + (halfq ? 2 : 0);
#pragma unroll
            for (int sp = 0; sp < 2; ++sp) {
                const int pkt = sp * 4 + q;
                const uint32_t* hp = sp ? h1 : h0;
#pragma unroll
                for (int cc = 0; cc < 4; ++cc)
                    sA[(((mt * 8 + pkt) * 32) + 4 * (rr & 7) + cc) * 4 + wsel] = hp[cc];
            }
        }
        __syncthreads();

        float best[4];
        int   bidx[4];
#pragma unroll
        for (int h = 0; h < 4; ++h) { best[h] = 3.4e38f; bidx[h] = 0; }

        for (int ch = 0; ch < NCH; ++ch) {
            if (ch < NCH - 1) asm volatile("cp.async.wait_group 1;" ::: "memory");
            else              asm volatile("cp.async.wait_group 0;" ::: "memory");
            __syncthreads();
            const uint32_t* Bb = (const uint32_t*)(sm + P2_SB + (ch & 1) * CHB);

            float acc[2][2][4];
#pragma unroll
            for (int m = 0; m < 2; ++m)
#pragma unroll
                for (int n = 0; n < 2; ++n)
#pragma unroll
                    for (int j = 0; j < 4; ++j) acc[m][n][j] = 0.f;

            // phase 1: x0*e1 and x1*e0
#pragma unroll
            for (int lkt = 0; lkt < 8; ++lkt) {
                const int qq = lkt & 3;
                const int pa = (lkt < 4) ? qq : (4 + qq);
                const int pb = (lkt < 4) ? (4 + qq) : qq;
                uint4 Af[2];
#pragma unroll
                for (int m = 0; m < 2; ++m)
                    Af[m] = *(const uint4*)(sA + ((((rg * 2 + m) * 8 + pa) * 32) + lane) * 4);
#pragma unroll
                for (int n = 0; n < 2; ++n) {
                    uint2 Bf = *(const uint2*)(Bb + (((pb * 16 + cg * 2 + n) * 32) + lane) * 2);
#pragma unroll
                    for (int m = 0; m < 2; ++m) mma16816(acc[m][n], Af[m], Bf);
                }
            }
#pragma unroll
            for (int m = 0; m < 2; ++m)
#pragma unroll
                for (int n = 0; n < 2; ++n)
#pragma unroll
                    for (int j = 0; j < 4; ++j) acc[m][n][j] *= INV2048;
            // phase 2: x0*e0
#pragma unroll
            for (int qq = 0; qq < 4; ++qq) {
                uint4 Af[2];
#pragma unroll
                for (int m = 0; m < 2; ++m)
                    Af[m] = *(const uint4*)(sA + ((((rg * 2 + m) * 8 + qq) * 32) + lane) * 4);
#pragma unroll
                for (int n = 0; n < 2; ++n) {
                    uint2 Bf = *(const uint2*)(Bb + (((qq * 16 + cg * 2 + n) * 32) + lane) * 2);
#pragma unroll
                    for (int m = 0; m < 2; ++m) mma16816(acc[m][n], Af[m], Bf);
                }
            }
            __syncthreads();

            if (ch + 2 < NCH) {
                const char* src = (const char*)g_Bp + (size_t)(ch + 2) * CHB;
                const uint32_t dst = sBaddr + (ch & 1) * CHB;
                for (int k = tid; k < CHB / 16; k += 512) cp16(dst + k * 16, src + k * 16);
                cp_commit();
            }

            const int cb = ch * 128 + cg * 16 + 2 * (lane & 3);
#pragma unroll
            for (int n = 0; n < 2; ++n) {
                const int c0 = cb + n * 8;
                const float ea = sE2[c0], eb = sE2[c0 + 1];
#pragma unroll
                for (int m = 0; m < 2; ++m) {
                    const int ha = 2 * m, hb = 2 * m + 1;
                    float s0 = fmaf(-2.f, acc[m][n][0], ea);
                    float s1 = fmaf(-2.f, acc[m][n][1], eb);
                    float s2 = fmaf(-2.f, acc[m][n][2], ea);
                    float s3 = fmaf(-2.f, acc[m][n][3], eb);
                    if (s0 < best[ha]) { best[ha] = s0; bidx[ha] = c0; }
                    if (s1 < best[ha]) { best[ha] = s1; bidx[ha] = c0 + 1; }
                    if (s2 < best[hb]) { best[hb] = s2; bidx[hb] = c0; }
                    if (s3 < best[hb]) { best[hb] = s3; bidx[hb] = c0 + 1; }
                }
            }
        }

#pragma unroll
        for (int h = 0; h < 4; ++h) {
#pragma unroll
            for (int off = 1; off < 4; off <<= 1) {
                float os = __shfl_xor_sync(0xffffffffu, best[h], off);
                int   oi = __shfl_xor_sync(0xffffffffu, bidx[h], off);
                if (os < best[h] || (os == best[h] && oi < bidx[h])) { best[h] = os; bidx[h] = oi; }
            }
        }
        if ((lane & 3) == 0) {
            const int q = lane >> 2;
#pragma unroll
            for (int h = 0; h < 4; ++h) {
                const int m = h >> 1, hb = h & 1;
                const int row = rg * 32 + m * 16 + hb * 8 + q;
                sRF[row * 8 + cg] = best[h];
                sRI[row * 8 + cg] = bidx[h];
            }
        }
        __syncthreads();
        if (tid < ROWS_CTA && sL[tid] >= 0) {
            float bv = sRF[tid * 8];
            int   bi = sRI[tid * 8];
#pragma unroll
            for (int g = 1; g < 8; ++g) {
                float v = sRF[tid * 8 + g];
                int   i = sRI[tid * 8 + g];
                if (v < bv || (v == bv && i < bi)) { bv = v; bi = i; }
            }
            const int grow = sL[tid];
            g_idx[grow] = bi;
            out_idxf[grow] = (float)bi;
            atomicAdd(&g_counts[bi], 1);
        }
        __syncthreads();
    }
}

// ---------------- gather + straight-through + commitment loss + fused finalize ----------------
__global__ void __launch_bounds__(256)
gather_fin_kernel(const float* __restrict__ x, const float* __restrict__ embed,
                  float* __restrict__ out) {
    __shared__ float warpsum[8];
    __shared__ int s_last;
    const int tid = threadIdx.x, lane = tid & 31, w = tid >> 5;
    const int row = blockIdx.x * 256 + tid;   // row = b*2048 + t
    const int b_i = row >> 11, t_i = row & (TT - 1);

    const int bi = g_idx[row];
    out[IDX_OFF + row] = (float)bi;    // idx also (re)written here is fine? No — already written.
    // NOTE: rewriting identical value keeps determinism.

    const float4* ep = (const float4*)(embed + (size_t)bi * DIM);
    const float* xp = x + (size_t)b_i * (DIM * TT) + t_i;
    float* op = out + (size_t)b_i * (DIM * TT) + t_i;
    float s = 0.f;
#pragma unroll
    for (int j = 0; j < 16; ++j) {
        float4 e = ep[j];
        float x0 = xp[(size_t)(4 * j) * TT];
        float x1 = xp[(size_t)(4 * j + 1) * TT];
        float x2 = xp[(size_t)(4 * j + 2) * TT];
        float x3 = xp[(size_t)(4 * j + 3) * TT];
        float d0 = e.x - x0, d1 = e.y - x1, d2 = e.z - x2, d3 = e.w - x3;
        op[(size_t)(4 * j) * TT]     = x0 + d0;
        op[(size_t)(4 * j + 1) * TT] = x1 + d1;
        op[(size_t)(4 * j + 2) * TT] = x2 + d2;
        op[(size_t)(4 * j + 3) * TT] = x3 + d3;
        s += d0 * d0 + d1 * d1 + d2 * d2 + d3 * d3;
    }
#pragma unroll
    for (int o = 16; o; o >>= 1) s += __shfl_down_sync(0xffffffffu, s, o);
    if (lane == 0) warpsum[w] = s;
    __syncthreads();
    if (w == 0) {
        float v = (lane < 8) ? warpsum[lane] : 0.f;
#pragma unroll
        for (int o = 4; o; o >>= 1) v += __shfl_down_sync(0xffffffffu, v, o);
        if (lane == 0) atomicAdd(&g_sumsq, v);
    }

    // last-block finalize
    if (tid == 0) {
        __threadfence();
        s_last = (atomicAdd(&g_gdone, 1) == (int)gridDim.x - 1);
    }
    __syncthreads();
    if (!s_last) return;
    __threadfence();

    {
        __shared__ float f1[8], f2[8];
        float t1 = 0.f, t2 = 0.f;
        for (int c = tid; c < NUM_E; c += 256) {
            float p = (float)g_counts[c] * (1.0f / (float)NROWS);
            out[AVG_OFF + c] = p;
            t1 += p * logf(p + 1e-10f);
            t2 += p * logf(p * (float)NUM_E + 1e-10f);
        }
#pragma unroll
        for (int o = 16; o; o >>= 1) {
            t1 += __shfl_down_sync(0xffffffffu, t1, o);
            t2 += __shfl_down_sync(0xffffffffu, t2, o);
        }
        if (lane == 0) { f1[w] = t1; f2[w] = t2; }
        __syncthreads();
        if (w == 0) {
            float a = (lane < 8) ? f1[lane] : 0.f;
            float b = (lane < 8) ? f2[lane] : 0.f;
#pragma unroll
            for (int o = 4; o; o >>= 1) {
                a += __shfl_down_sync(0xffffffffu, a, o);
                b += __shfl_down_sync(0xffffffffu, b, o);
            }
            if (lane == 0) {
                out[PERP_OFF]   = expf(-a);
                out[USAGE_OFF]  = b;
                out[COMMIT_OFF] = 0.25f * g_sumsq / (float)NELEM;
            }
        }
    }
}

extern "C" void kernel_launch(void* const* d_in, const int* in_sizes, int n_in,
                              void* d_out, int out_size) {
    const float* x     = (const float*)d_in[0];
    const float* embed = (const float*)d_in[1];
    float* out = (float*)d_out;

    cudaFuncSetAttribute(vq_mma_kernel, cudaFuncAttributeMaxDynamicSharedMemorySize, SMEM_MAIN);
    cudaFuncSetAttribute(pass2_kernel, cudaFuncAttributeMaxDynamicSharedMemorySize, SMEM_P2);

    prep_kernel<<<32, 32>>>(embed);
    vq_mma_kernel<<<NROWS / ROWS_CTA, 512, SMEM_MAIN>>>(x, out + IDX_OFF);
    pass2_kernel<<<296, 512, SMEM_P2>>>(x, out + IDX_OFF);
    gather_fin_kernel<<<NROWS / 256, 256>>>(x, embed, out);
    finalize_placeholder:;
}

// round 11
// speedup vs baseline: 2.3736x; 1.0901x over previous
#include <cuda_runtime.h>
#include <cuda_fp16.h>
#include <cstdint>
#include <math.h>

// ---------------- problem constants ----------------
#define NUM_E 1024
#define DIM   64
#define TT    2048
#define BB    32
#define NROWS (BB * TT)          // 65536
#define NELEM (BB * DIM * TT)    // 4194304

// output layout (flattened tuple, fp32)
#define COMMIT_OFF 4194304
#define PERP_OFF   4194305
#define AVG_OFF    4194306
#define IDX_OFF    4195330
#define USAGE_OFF  4260866

// ---------------- tiling ----------------
#define ROWS_CTA 64                  // rows per CTA (4 m-tiles)
#define NCH      8                   // code chunks of 128
#define CHB      32768               // full 2-split packed chunk (8 pkt)
#define CHB2     16384               // split0 half (4 pkt)
#define INV2048  4.8828125e-4f

// ---- main kernel smem ----
#define SA_OFF   0                   // A frags split0: 8KB
#define SB_OFF   8192                // B split0 frags: 128KB
#define SE2_OFF  139264              // 4KB
#define SXN_OFF  143360
#define SRN_OFF  143616
#define SB1_OFF  143872
#define SI1_OFF  145920
#define SB2_OFF  147968
#define SMEM_MAIN 150528

// ---- pass2 kernel smem ----
#define P2_SA    0                   // A frags 2-split: 16KB
#define P2_SB    16384               // 2 * 32KB
#define P2_SE2   81920               // 4KB
#define P2_SRF   86016               // 64*8*4
#define P2_SRI   88064               // 64*8*4
#define P2_SL    90112               // 64*4
#define SMEM_P2  90368

// ---------------- device scratch ----------------
__device__ __align__(16) unsigned char g_Bp[NCH * CHB];  // 2-split packed B
__device__ float g_e2[NUM_E];
__device__ float g_hm2[32];
__device__ float g_e0m2[32];
__device__ int   g_idx[NROWS];                 // -1 = flagged
__device__ unsigned long long g_slot[NROWS];   // packed (okey(score)<<10|idx)
__device__ int   g_list[NROWS];
__device__ int   g_cnt;
__device__ int   g_gdone;
__device__ int   g_counts[NUM_E];
__device__ float g_sumsq;

// ---------------- helpers ----------------
__device__ __forceinline__ uint32_t smem_u32(const void* p) {
    uint32_t a;
    asm("{ .reg .u64 t; cvta.to.shared.u64 t, %1; cvt.u32.u64 %0, t; }" : "=r"(a) : "l"(p));
    return a;
}
__device__ __forceinline__ void cp16(uint32_t saddr, const void* g) {
    asm volatile("cp.async.cg.shared.global [%0], [%1], 16;" :: "r"(saddr), "l"(g));
}
__device__ __forceinline__ void cp_commit() {
    asm volatile("cp.async.commit_group;" ::: "memory");
}
__device__ __forceinline__ void mma16816(float* d, const uint4 a, const uint2 b) {
    asm volatile(
        "mma.sync.aligned.m16n8k16.row.col.f32.f16.f16.f32 "
        "{%0,%1,%2,%3}, {%4,%5,%6,%7}, {%8,%9}, {%0,%1,%2,%3};"
        : "+f"(d[0]), "+f"(d[1]), "+f"(d[2]), "+f"(d[3])
        : "r"(a.x), "r"(a.y), "r"(a.z), "r"(a.w), "r"(b.x), "r"(b.y));
}
__device__ __forceinline__ void split2(float v, uint32_t& u0, uint32_t& u1) {
    __half h0 = __float2half_rn(v);
    float f0 = __half2float(h0);
    __half h1 = __float2half_rn((v - f0) * 2048.0f);
    u0 = (uint32_t)__half_as_ushort(h0);
    u1 = (uint32_t)__half_as_ushort(h1);
}
__device__ __forceinline__ uint32_t okey(float f) {
    uint32_t b = __float_as_uint(f);
    return (b & 0x80000000u) ? ~b : (b | 0x80000000u);
}

// ---------------- prep ----------------
__global__ void prep_kernel(const float* __restrict__ embed) {
    const int c = blockIdx.x * 32 + threadIdx.x;
    const float* e = embed + (size_t)c * DIM;
    uint32_t h0[32], h1[32];
    float e2 = 0.f, e02 = 0.f, res2 = 0.f;
#pragma unroll 8
    for (int j = 0; j < 32; ++j) {
        float2 v = *(const float2*)(e + 2 * j);
        e2 += v.x * v.x + v.y * v.y;
        uint32_t a0, a1, b0, b1;
        split2(v.x, a0, a1);
        split2(v.y, b0, b1);
        float fa = __half2float(__ushort_as_half((unsigned short)a0));
        float fb = __half2float(__ushort_as_half((unsigned short)b0));
        e02 += fa * fa + fb * fb;
        float rx = v.x - fa, ry = v.y - fb;
        res2 += rx * rx + ry * ry;
        h0[j] = a0 | (b0 << 16);
        h1[j] = a1 | (b1 << 16);
    }
    g_e2[c] = e2;
    g_counts[c] = 0;
    if (c == 0) { g_sumsq = 0.f; g_cnt = 0; g_gdone = 0; }
    for (int i = c; i < NROWS; i += 1024) g_slot[i] = 0xFFFFFFFFFFFFFFFFull;

    const int chunk = c >> 7, n_in = c & 127, nt = n_in >> 3, lq = n_in & 7;
    uint32_t* dstb = (uint32_t*)(g_Bp + (size_t)chunk * CHB);
#pragma unroll
    for (int pkt = 0; pkt < 8; ++pkt) {
        const uint32_t* hp = (pkt < 4) ? h0 : h1;
        const int kb = (pkt & 3) * 8;
#pragma unroll
        for (int cc = 0; cc < 4; ++cc) {
            uint32_t* d = dstb + (((pkt * 16 + nt) * 32) + 4 * lq + cc) * 2;
            d[0] = hp[kb + cc];
            d[1] = hp[kb + 4 + cc];
        }
    }
#pragma unroll
    for (int o = 16; o; o >>= 1) {
        res2 = fmaxf(res2, __shfl_xor_sync(0xffffffffu, res2, o));
        e02  = fmaxf(e02,  __shfl_xor_sync(0xffffffffu, e02,  o));
    }
    if (threadIdx.x == 0) { g_hm2[blockIdx.x] = res2; g_e0m2[blockIdx.x] = e02; }
}

// ---------------- main: 1-product HMMA + top-2 + sound flag ----------------
__global__ void __launch_bounds__(512, 1)
vq_mma_kernel(const float* __restrict__ x) {
    extern __shared__ char sm[];
    uint32_t* sA  = (uint32_t*)(sm + SA_OFF);
    float*    sE2 = (float*)(sm + SE2_OFF);
    float*    sXn = (float*)(sm + SXN_OFF);
    float*    sRn = (float*)(sm + SRN_OFF);
    float*    sB1 = (float*)(sm + SB1_OFF);
    int*      sI1 = (int*)(sm + SI1_OFF);
    float*    sB2 = (float*)(sm + SB2_OFF);
    const uint32_t sBaddr = smem_u32(sm + SB_OFF);

    const int tid = threadIdx.x, lane = tid & 31, w = tid >> 5;
    const int rg = w >> 3, cg = w & 7;

    // load split0 halves of all 8 chunks (128KB)
    for (int k = tid; k < 8192; k += 512) {
        const int chk = k >> 10, off = k & 1023;
        cp16(sBaddr + k * 16, (const char*)g_Bp + (size_t)chk * CHB + off * 16);
    }
    cp_commit();

    {
        const int r = tid >> 3, o = tid & 7;
        const int q = o >> 1, halfq = o & 1;
        const int grow = blockIdx.x * ROWS_CTA + r;
        const float* xp = x + (size_t)(grow >> 11) * (DIM * TT) + (grow & (TT - 1));
        uint32_t h0[4];
        float x2 = 0.f, xi2 = 0.f;
#pragma unroll
        for (int j = 0; j < 4; ++j) {
            float va = xp[(size_t)(8 * o + 2 * j) * TT];
            float vb = xp[(size_t)(8 * o + 2 * j + 1) * TT];
            __half ha = __float2half_rn(va), hb = __float2half_rn(vb);
            float fa = __half2float(ha), fb = __half2float(hb);
            float ra = va - fa, rb = vb - fb;
            x2 += va * va + vb * vb;
            xi2 += ra * ra + rb * rb;
            h0[j] = (uint32_t)__half_as_ushort(ha) | ((uint32_t)__half_as_ushort(hb) << 16);
        }
#pragma unroll
        for (int off = 1; off < 8; off <<= 1) {
            x2  += __shfl_xor_sync(0xffffffffu, x2,  off);
            xi2 += __shfl_xor_sync(0xffffffffu, xi2, off);
        }
        if (o == 0) { sXn[r] = sqrtf(x2); sRn[r] = sqrtf(xi2); }

        const int mt = r >> 4, rr = r & 15;
        const int wsel = ((rr < 8) ? 0 : 1) + (halfq ? 2 : 0);
#pragma unroll
        for (int cc = 0; cc < 4; ++cc)
            sA[(((mt * 4 + q) * 32) + 4 * (rr & 7) + cc) * 4 + wsel] = h0[cc];
        for (int i = tid; i < NUM_E; i += 512) sE2[i] = g_e2[i];
    }
    asm volatile("cp.async.wait_group 0;" ::: "memory");
    __syncthreads();

    float b1_[4] = {3.4e38f, 3.4e38f, 3.4e38f, 3.4e38f};
    float b2_[4] = {3.4e38f, 3.4e38f, 3.4e38f, 3.4e38f};
    int   i1_[4] = {0, 0, 0, 0};

#define UPD(h, s, c) do { \
        if ((s) < b1_[h]) { b2_[h] = b1_[h]; b1_[h] = (s); i1_[h] = (c); } \
        else if ((s) < b2_[h]) b2_[h] = (s); \
    } while (0)

    for (int ch = 0; ch < NCH; ++ch) {
        const uint32_t* Bb = (const uint32_t*)(sm + SB_OFF + ch * CHB2);
        float acc[2][2][4];
#pragma unroll
        for (int m = 0; m < 2; ++m)
#pragma unroll
            for (int n = 0; n < 2; ++n)
#pragma unroll
                for (int j = 0; j < 4; ++j) acc[m][n][j] = 0.f;
#pragma unroll
        for (int kt = 0; kt < 4; ++kt) {
            uint4 Af[2];
#pragma unroll
            for (int m = 0; m < 2; ++m)
                Af[m] = *(const uint4*)(sA + ((((rg * 2 + m) * 4 + kt) * 32) + lane) * 4);
#pragma unroll
            for (int n = 0; n < 2; ++n) {
                uint2 Bf = *(const uint2*)(Bb + (((kt * 16 + cg * 2 + n) * 32) + lane) * 2);
#pragma unroll
                for (int m = 0; m < 2; ++m) mma16816(acc[m][n], Af[m], Bf);
            }
        }
        const int cb = ch * 128 + cg * 16 + 2 * (lane & 3);
#pragma unroll
        for (int n = 0; n < 2; ++n) {
            const int c0 = cb + n * 8;
            const float ea = sE2[c0], eb = sE2[c0 + 1];
#pragma unroll
            for (int m = 0; m < 2; ++m) {
                const int ha = 2 * m, hb = 2 * m + 1;
                float s0 = fmaf(-2.f, acc[m][n][0], ea);
                float s1 = fmaf(-2.f, acc[m][n][1], eb);
                float s2 = fmaf(-2.f, acc[m][n][2], ea);
                float s3 = fmaf(-2.f, acc[m][n][3], eb);
                UPD(ha, s0, c0); UPD(ha, s1, c0 + 1);
                UPD(hb, s2, c0); UPD(hb, s3, c0 + 1);
            }
        }
    }
#undef UPD

#pragma unroll
    for (int h = 0; h < 4; ++h) {
#pragma unroll
        for (int off = 1; off < 4; off <<= 1) {
            float ob1 = __shfl_xor_sync(0xffffffffu, b1_[h], off);
            int   oi1 = __shfl_xor_sync(0xffffffffu, i1_[h], off);
            float ob2 = __shfl_xor_sync(0xffffffffu, b2_[h], off);
            if (ob1 < b1_[h] || (ob1 == b1_[h] && oi1 < i1_[h])) {
                b2_[h] = fminf(b1_[h], ob2);
                b1_[h] = ob1; i1_[h] = oi1;
            } else {
                b2_[h] = fminf(b2_[h], ob1);
            }
        }
    }
    if ((lane & 3) == 0) {
        const int q = lane >> 2;
#pragma unroll
        for (int h = 0; h < 4; ++h) {
            const int m = h >> 1, hb = h & 1;
            const int row = rg * 32 + m * 16 + hb * 8 + q;
            sB1[row * 8 + cg] = b1_[h];
            sI1[row * 8 + cg] = i1_[h];
            sB2[row * 8 + cg] = b2_[h];
        }
    }
    __syncthreads();

    if (tid < ROWS_CTA) {
        float B1 = sB1[tid * 8], B2 = sB2[tid * 8];
        int   I1 = sI1[tid * 8];
#pragma unroll
        for (int g = 1; g < 8; ++g) {
            float ob1 = sB1[tid * 8 + g], ob2 = sB2[tid * 8 + g];
            int   oi1 = sI1[tid * 8 + g];
            if (ob1 < B1 || (ob1 == B1 && oi1 < I1)) {
                B2 = fminf(B1, ob2);
                B1 = ob1; I1 = oi1;
            } else {
                B2 = fminf(B2, ob1);
            }
        }
        float hm2 = g_hm2[0], e0m2 = g_e0m2[0];
#pragma unroll
        for (int i = 1; i < 32; ++i) {
            hm2 = fmaxf(hm2, g_hm2[i]);
            e0m2 = fmaxf(e0m2, g_e0m2[i]);
        }
        const float Wt = 4.0f * (sXn[tid] * sqrtf(hm2) + sRn[tid] * sqrtf(e0m2)) + 0.02f;
        const int grow = blockIdx.x * ROWS_CTA + tid;
        if (B2 - B1 > Wt) {
            g_idx[grow] = I1;
            atomicAdd(&g_counts[I1], 1);
        } else {
            g_idx[grow] = -1;
            const int pos = atomicAdd(&g_cnt, 1);
            g_list[pos] = grow;
        }
    }
}

// ---------------- pass2: exact 2-split HMMA rescore, half-tiles (64 rows x 512 codes) ----------------
__global__ void __launch_bounds__(512, 2)
pass2_kernel(const float* __restrict__ x) {
    extern __shared__ char sm[];
    uint32_t* sA  = (uint32_t*)(sm + P2_SA);
    float*    sE2 = (float*)(sm + P2_SE2);
    float*    sRF = (float*)(sm + P2_SRF);
    int*      sRI = (int*)(sm + P2_SRI);
    int*      sL  = (int*)(sm + P2_SL);
    const uint32_t sBaddr = smem_u32(sm + P2_SB);

    const int tid = threadIdx.x, lane = tid & 31, w = tid >> 5;
    const int rg = w >> 3, cg = w & 7;
    const int cnt = g_cnt;

    for (int i = tid; i < NUM_E; i += 512) sE2[i] = g_e2[i];

    // half-tile ht: pair = ht>>1 (64 rows), codehalf = ht&1 (512 codes)
    // FIX (R10 bug): bound must cover BOTH halves of the last partial pair.
    for (int ht = blockIdx.x; (ht >> 1) * 64 < cnt; ht += gridDim.x) {
        const int pair = ht >> 1, chalf = ht & 1;
        const int c0ch = chalf * 4;   // first chunk of this half

        if (tid < ROWS_CTA) {
            const int p = pair * ROWS_CTA + tid;
            sL[tid] = (p < cnt) ? g_list[p] : -1;
        }
        __syncthreads();

        // prefetch chunks c0ch, c0ch+1 (full 2-split)
        for (int k = tid; k < CHB / 16; k += 512)
            cp16(sBaddr + k * 16, (const char*)g_Bp + (size_t)c0ch * CHB + k * 16);
        cp_commit();
        for (int k = tid; k < CHB / 16; k += 512)
            cp16(sBaddr + CHB + k * 16, (const char*)g_Bp + (size_t)(c0ch + 1) * CHB + k * 16);
        cp_commit();

        // A build (2-split), indirect rows
        {
            const int r = tid >> 3, o = tid & 7;
            const int q = o >> 1, halfq = o & 1;
            int grow = sL[r];
            if (grow < 0) grow = 0;
            const float* xp = x + (size_t)(grow >> 11) * (DIM * TT) + (grow & (TT - 1));
            uint32_t h0[4], h1[4];
#pragma unroll
            for (int j = 0; j < 4; ++j) {
                float va = xp[(size_t)(8 * o + 2 * j) * TT];
                float vb = xp[(size_t)(8 * o + 2 * j + 1) * TT];
                uint32_t a0, a1, b0, b1;
                split2(va, a0, a1);
                split2(vb, b0, b1);
                h0[j] = a0 | (b0 << 16);
                h1[j] = a1 | (b1 << 16);
            }
            const int mt = r >> 4, rr = r & 15;
            const int wsel = ((rr < 8) ? 0 : 1) + (halfq ? 2 : 0);
#pragma unroll
            for (int sp = 0; sp < 2; ++sp) {
                const int pkt = sp * 4 + q;
                const uint32_t* hp = sp ? h1 : h0;
#pragma unroll
                for (int cc = 0; cc < 4; ++cc)
                    sA[(((mt * 8 + pkt) * 32) + 4 * (rr & 7) + cc) * 4 + wsel] = hp[cc];
            }
        }
        __syncthreads();

        float best[4];
        int   bidx[4];
#pragma unroll
        for (int h = 0; h < 4; ++h) { best[h] = 3.4e38f; bidx[h] = 0; }

        for (int ch = 0; ch < 4; ++ch) {
            if (ch < 3) asm volatile("cp.async.wait_group 1;" ::: "memory");
            else        asm volatile("cp.async.wait_group 0;" ::: "memory");
            __syncthreads();
            const uint32_t* Bb = (const uint32_t*)(sm + P2_SB + (ch & 1) * CHB);

            float acc[2][2][4];
#pragma unroll
            for (int m = 0; m < 2; ++m)
#pragma unroll
                for (int n = 0; n < 2; ++n)
#pragma unroll
                    for (int j = 0; j < 4; ++j) acc[m][n][j] = 0.f;

            // phase 1: x0*e1 and x1*e0
#pragma unroll
            for (int lkt = 0; lkt < 8; ++lkt) {
                const int qq = lkt & 3;
                const int pa = (lkt < 4) ? qq : (4 + qq);
                const int pb = (lkt < 4) ? (4 + qq) : qq;
                uint4 Af[2];
#pragma unroll
                for (int m = 0; m < 2; ++m)
                    Af[m] = *(const uint4*)(sA + ((((rg * 2 + m) * 8 + pa) * 32) + lane) * 4);
#pragma unroll
                for (int n = 0; n < 2; ++n) {
                    uint2 Bf = *(const uint2*)(Bb + (((pb * 16 + cg * 2 + n) * 32) + lane) * 2);
#pragma unroll
                    for (int m = 0; m < 2; ++m) mma16816(acc[m][n], Af[m], Bf);
                }
            }
#pragma unroll
            for (int m = 0; m < 2; ++m)
#pragma unroll
                for (int n = 0; n < 2; ++n)
#pragma unroll
                    for (int j = 0; j < 4; ++j) acc[m][n][j] *= INV2048;
            // phase 2: x0*e0
#pragma unroll
            for (int qq = 0; qq < 4; ++qq) {
                uint4 Af[2];
#pragma unroll
                for (int m = 0; m < 2; ++m)
                    Af[m] = *(const uint4*)(sA + ((((rg * 2 + m) * 8 + qq) * 32) + lane) * 4);
#pragma unroll
                for (int n = 0; n < 2; ++n) {
                    uint2 Bf = *(const uint2*)(Bb + (((qq * 16 + cg * 2 + n) * 32) + lane) * 2);
#pragma unroll
                    for (int m = 0; m < 2; ++m) mma16816(acc[m][n], Af[m], Bf);
                }
            }
            __syncthreads();

            if (ch + 2 < 4) {
                const char* src = (const char*)g_Bp + (size_t)(c0ch + ch + 2) * CHB;
                const uint32_t dst = sBaddr + (ch & 1) * CHB;
                for (int k = tid; k < CHB / 16; k += 512) cp16(dst + k * 16, src + k * 16);
                cp_commit();
            }

            const int cb = (c0ch + ch) * 128 + cg * 16 + 2 * (lane & 3);
#pragma unroll
            for (int n = 0; n < 2; ++n) {
                const int c0 = cb + n * 8;
                const float ea = sE2[c0], eb = sE2[c0 + 1];
#pragma unroll
                for (int m = 0; m < 2; ++m) {
                    const int ha = 2 * m, hb = 2 * m + 1;
                    float s0 = fmaf(-2.f, acc[m][n][0], ea);
                    float s1 = fmaf(-2.f, acc[m][n][1], eb);
                    float s2 = fmaf(-2.f, acc[m][n][2], ea);
                    float s3 = fmaf(-2.f, acc[m][n][3], eb);
                    if (s0 < best[ha]) { best[ha] = s0; bidx[ha] = c0; }
                    if (s1 < best[ha]) { best[ha] = s1; bidx[ha] = c0 + 1; }
                    if (s2 < best[hb]) { best[hb] = s2; bidx[hb] = c0; }
                    if (s3 < best[hb]) { best[hb] = s3; bidx[hb] = c0 + 1; }
                }
            }
        }

#pragma unroll
        for (int h = 0; h < 4; ++h) {
#pragma unroll
            for (int off = 1; off < 4; off <<= 1) {
                float os = __shfl_xor_sync(0xffffffffu, best[h], off);
                int   oi = __shfl_xor_sync(0xffffffffu, bidx[h], off);
                if (os < best[h] || (os == best[h] && oi < bidx[h])) { best[h] = os; bidx[h] = oi; }
            }
        }
        if ((lane & 3) == 0) {
            const int q = lane >> 2;
#pragma unroll
            for (int h = 0; h < 4; ++h) {
                const int m = h >> 1, hb = h & 1;
                const int row = rg * 32 + m * 16 + hb * 8 + q;
                sRF[row * 8 + cg] = best[h];
                sRI[row * 8 + cg] = bidx[h];
            }
        }
        __syncthreads();
        if (tid < ROWS_CTA && sL[tid] >= 0) {
            float bv = sRF[tid * 8];
            int   bi = sRI[tid * 8];
#pragma unroll
            for (int g = 1; g < 8; ++g) {
                float v = sRF[tid * 8 + g];
                int   i = sRI[tid * 8 + g];
                if (v < bv || (v == bv && i < bi)) { bv = v; bi = i; }
            }
            const unsigned long long key =
                ((unsigned long long)okey(bv) << 10) | (unsigned long long)bi;
            atomicMin(&g_slot[sL[tid]], key);
        }
        __syncthreads();
    }
}

// ---------------- gather + straight-through + losses + fused finalize ----------------
// block 256 = 64 rows x 4 dim-quarters; lanes consecutive in t -> 128B coalesced
__global__ void __launch_bounds__(256)
gather_fin_kernel(const float* __restrict__ x, const float* __restrict__ embed,
                  float* __restrict__ out) {
    __shared__ float warpsum[8];
    __shared__ int s_last;
    const int tid = threadIdx.x, lane = tid & 31, w = tid >> 5;
    const int r = tid & 63, q = tid >> 6;
    const int row = blockIdx.x * 64 + r;
    const int b_i = row >> 11, t_i = row & (TT - 1);

    const int idx0 = g_idx[row];
    int bi = idx0;
    if (bi < 0) bi = (int)(g_slot[row] & 1023ull);
    if (q == 0) {
        out[IDX_OFF + row] = (float)bi;
        if (idx0 < 0) atomicAdd(&g_counts[bi], 1);
    }

    const float4* ep = (const float4*)(embed + (size_t)bi * DIM + q * 16);
    const float* xp = x + ((size_t)b_i * DIM + q * 16) * TT + t_i;
    float* op = out + ((size_t)b_i * DIM + q * 16) * TT + t_i;
    float s = 0.f;
#pragma unroll
    for (int j = 0; j < 4; ++j) {
        float4 e = ep[j];
        float x0 = xp[(size_t)(4 * j) * TT];
        float x1 = xp[(size_t)(4 * j + 1) * TT];
        float x2 = xp[(size_t)(4 * j + 2) * TT];
        float x3 = xp[(size_t)(4 * j + 3) * TT];
        float d0 = e.x - x0, d1 = e.y - x1, d2 = e.z - x2, d3 = e.w - x3;
        op[(size_t)(4 * j) * TT]     = x0 + d0;
        op[(size_t)(4 * j + 1) * TT] = x1 + d1;
        op[(size_t)(4 * j + 2) * TT] = x2 + d2;
        op[(size_t)(4 * j + 3) * TT] = x3 + d3;
        s += d0 * d0 + d1 * d1 + d2 * d2 + d3 * d3;
    }
#pragma unroll
    for (int o = 16; o; o >>= 1) s += __shfl_down_sync(0xffffffffu, s, o);
    if (lane == 0) warpsum[w] = s;
    __syncthreads();
    if (w == 0) {
        float v = (lane < 8) ? warpsum[lane] : 0.f;
#pragma unroll
        for (int o = 4; o; o >>= 1) v += __shfl_down_sync(0xffffffffu, v, o);
        if (lane == 0) atomicAdd(&g_sumsq, v);
    }

    if (tid == 0) {
        __threadfence();
        s_last = (atomicAdd(&g_gdone, 1) == (int)gridDim.x - 1);
    }
    __syncthreads();
    if (!s_last) return;
    __threadfence();

    {
        __shared__ float f1[8], f2[8];
        float t1 = 0.f, t2 = 0.f;
        for (int c = tid; c < NUM_E; c += 256) {
            float p = (float)g_counts[c] * (1.0f / (float)NROWS);
            out[AVG_OFF + c] = p;
            t1 += p * logf(p + 1e-10f);
            t2 += p * logf(p * (float)NUM_E + 1e-10f);
        }
#pragma unroll
        for (int o = 16; o; o >>= 1) {
            t1 += __shfl_down_sync(0xffffffffu, t1, o);
            t2 += __shfl_down_sync(0xffffffffu, t2, o);
        }
        if (lane == 0) { f1[w] = t1; f2[w] = t2; }
        __syncthreads();
        if (w == 0) {
            float a = (lane < 8) ? f1[lane] : 0.f;
            float b = (lane < 8) ? f2[lane] : 0.f;
#pragma unroll
            for (int o = 4; o; o >>= 1) {
                a += __shfl_down_sync(0xffffffffu, a, o);
                b += __shfl_down_sync(0xffffffffu, b, o);
            }
            if (lane == 0) {
                out[PERP_OFF]   = expf(-a);
                out[USAGE_OFF]  = b;
                out[COMMIT_OFF] = 0.25f * g_sumsq / (float)NELEM;
            }
        }
    }
}

extern "C" void kernel_launch(void* const* d_in, const int* in_sizes, int n_in,
                              void* d_out, int out_size) {
    const float* x     = (const float*)d_in[0];
    const float* embed = (const float*)d_in[1];
    float* out = (float*)d_out;

    cudaFuncSetAttribute(vq_mma_kernel, cudaFuncAttributeMaxDynamicSharedMemorySize, SMEM_MAIN);
    cudaFuncSetAttribute(pass2_kernel, cudaFuncAttributeMaxDynamicSharedMemorySize, SMEM_P2);

    prep_kernel<<<32, 32>>>(embed);
    vq_mma_kernel<<<NROWS / ROWS_CTA, 512, SMEM_MAIN>>>(x);
    pass2_kernel<<<296, 512, SMEM_P2>>>(x);
    gather_fin_kernel<<<NROWS / 64, 256>>>(x, embed, out);
}

// round 12
// speedup vs baseline: 2.4761x; 1.0432x over previous
#include <cuda_runtime.h>
#include <cuda_fp16.h>
#include <cstdint>
#include <math.h>

// ---------------- problem constants ----------------
#define NUM_E 1024
#define DIM   64
#define TT    2048
#define BB    32
#define NROWS (BB * TT)          // 65536
#define NELEM (BB * DIM * TT)    // 4194304

// output layout (flattened tuple, fp32)
#define COMMIT_OFF 4194304
#define PERP_OFF   4194305
#define AVG_OFF    4194306
#define IDX_OFF    4195330
#define USAGE_OFF  4260866

// ---------------- tiling ----------------
#define ROWS_CTA 64                  // rows per tile (4 m-tiles)
#define NTILES   (NROWS / ROWS_CTA)  // 1024
#define NCH      8                   // code chunks of 128
#define CHB      32768               // full 2-split packed chunk (8 pkt)
#define CHB2     16384               // split0 half (4 pkt)
#define INV2048  4.8828125e-4f

// ---- main kernel smem ----
#define SA_OFF   0                   // A frags split0: 8KB
#define SB_OFF   8192                // B split0 frags: 128KB
#define SE2_OFF  139264              // 4KB
#define SXN_OFF  143360
#define SRN_OFF  143616
#define SB1_OFF  143872
#define SI1_OFF  145920
#define SB2_OFF  147968
#define SMEM_MAIN 150528

// ---- pass2 kernel smem ----
#define P2_SA    0                   // A frags 2-split: 16KB
#define P2_SB    16384               // 2 * 32KB
#define P2_SE2   81920               // 4KB
#define P2_SRF   86016               // 64*8*4
#define P2_SRI   88064               // 64*8*4
#define P2_SL    90112               // 64*4
#define SMEM_P2  90368

// ---------------- device scratch ----------------
__device__ __align__(16) unsigned char g_Bp[NCH * CHB];  // 2-split packed B
__device__ float g_e2[NUM_E];
__device__ float g_hm2[32];
__device__ float g_e0m2[32];
__device__ int   g_idx[NROWS];                 // -1 = flagged
__device__ unsigned long long g_slot[NROWS];   // packed (okey(score)<<10|idx)
__device__ int   g_list[NROWS];
__device__ int   g_cnt;
__device__ int   g_gdone;
__device__ int   g_counts[NUM_E];
__device__ float g_sumsq;

// ---------------- helpers ----------------
__device__ __forceinline__ uint32_t smem_u32(const void* p) {
    uint32_t a;
    asm("{ .reg .u64 t; cvta.to.shared.u64 t, %1; cvt.u32.u64 %0, t; }" : "=r"(a) : "l"(p));
    return a;
}
__device__ __forceinline__ void cp16(uint32_t saddr, const void* g) {
    asm volatile("cp.async.cg.shared.global [%0], [%1], 16;" :: "r"(saddr), "l"(g));
}
__device__ __forceinline__ void cp_commit() {
    asm volatile("cp.async.commit_group;" ::: "memory");
}
__device__ __forceinline__ void mma16816(float* d, const uint4 a, const uint2 b) {
    asm volatile(
        "mma.sync.aligned.m16n8k16.row.col.f32.f16.f16.f32 "
        "{%0,%1,%2,%3}, {%4,%5,%6,%7}, {%8,%9}, {%0,%1,%2,%3};"
        : "+f"(d[0]), "+f"(d[1]), "+f"(d[2]), "+f"(d[3])
        : "r"(a.x), "r"(a.y), "r"(a.z), "r"(a.w), "r"(b.x), "r"(b.y));
}
__device__ __forceinline__ void split2(float v, uint32_t& u0, uint32_t& u1) {
    __half h0 = __float2half_rn(v);
    float f0 = __half2float(h0);
    __half h1 = __float2half_rn((v - f0) * 2048.0f);
    u0 = (uint32_t)__half_as_ushort(h0);
    u1 = (uint32_t)__half_as_ushort(h1);
}
__device__ __forceinline__ uint32_t okey(float f) {
    uint32_t b = __float_as_uint(f);
    return (b & 0x80000000u) ? ~b : (b | 0x80000000u);
}

// ---------------- prep ----------------
__global__ void prep_kernel(const float* __restrict__ embed) {
    const int c = blockIdx.x * 32 + threadIdx.x;
    const float* e = embed + (size_t)c * DIM;
    uint32_t h0[32], h1[32];
    float e2 = 0.f, e02 = 0.f, res2 = 0.f;
#pragma unroll 8
    for (int j = 0; j < 32; ++j) {
        float2 v = *(const float2*)(e + 2 * j);
        e2 += v.x * v.x + v.y * v.y;
        uint32_t a0, a1, b0, b1;
        split2(v.x, a0, a1);
        split2(v.y, b0, b1);
        float fa = __half2float(__ushort_as_half((unsigned short)a0));
        float fb = __half2float(__ushort_as_half((unsigned short)b0));
        e02 += fa * fa + fb * fb;
        float rx = v.x - fa, ry = v.y - fb;
        res2 += rx * rx + ry * ry;
        h0[j] = a0 | (b0 << 16);
        h1[j] = a1 | (b1 << 16);
    }
    g_e2[c] = e2;
    g_counts[c] = 0;
    if (c == 0) { g_sumsq = 0.f; g_cnt = 0; g_gdone = 0; }
    for (int i = c; i < NROWS; i += 1024) g_slot[i] = 0xFFFFFFFFFFFFFFFFull;

    const int chunk = c >> 7, n_in = c & 127, nt = n_in >> 3, lq = n_in & 7;
    uint32_t* dstb = (uint32_t*)(g_Bp + (size_t)chunk * CHB);
#pragma unroll
    for (int pkt = 0; pkt < 8; ++pkt) {
        const uint32_t* hp = (pkt < 4) ? h0 : h1;
        const int kb = (pkt & 3) * 8;
#pragma unroll
        for (int cc = 0; cc < 4; ++cc) {
            uint32_t* d = dstb + (((pkt * 16 + nt) * 32) + 4 * lq + cc) * 2;
            d[0] = hp[kb + cc];
            d[1] = hp[kb + 4 + cc];
        }
    }
#pragma unroll
    for (int o = 16; o; o >>= 1) {
        res2 = fmaxf(res2, __shfl_xor_sync(0xffffffffu, res2, o));
        e02  = fmaxf(e02,  __shfl_xor_sync(0xffffffffu, e02,  o));
    }
    if (threadIdx.x == 0) { g_hm2[blockIdx.x] = res2; g_e0m2[blockIdx.x] = e02; }
}

// ---------------- main: persistent 1-product HMMA + top-2 + sound flag ----------------
// 148 persistent CTAs, tile-strided; B resident; x prefetched into registers.
__global__ void __launch_bounds__(512, 1)
vq_mma_kernel(const float* __restrict__ x) {
    extern __shared__ char sm[];
    uint32_t* sA  = (uint32_t*)(sm + SA_OFF);
    float*    sE2 = (float*)(sm + SE2_OFF);
    float*    sXn = (float*)(sm + SXN_OFF);
    float*    sRn = (float*)(sm + SRN_OFF);
    float*    sB1 = (float*)(sm + SB1_OFF);
    int*      sI1 = (int*)(sm + SI1_OFF);
    float*    sB2 = (float*)(sm + SB2_OFF);
    const uint32_t sBaddr = smem_u32(sm + SB_OFF);

    const int tid = threadIdx.x, lane = tid & 31, w = tid >> 5;
    const int rg = w >> 3, cg = w & 7;

    // load split0 halves of all 8 chunks (128KB) ONCE
    for (int k = tid; k < 8192; k += 512) {
        const int chk = k >> 10, off = k & 1023;
        cp16(sBaddr + k * 16, (const char*)g_Bp + (size_t)chk * CHB + off * 16);
    }
    cp_commit();
    for (int i = tid; i < NUM_E; i += 512) sE2[i] = g_e2[i];

    // error maxima (loop-invariant)
    float hm2 = g_hm2[0], e0m2 = g_e0m2[0];
#pragma unroll
    for (int i = 1; i < 32; ++i) {
        hm2 = fmaxf(hm2, g_hm2[i]);
        e0m2 = fmaxf(e0m2, g_e0m2[i]);
    }
    const float HM = sqrtf(hm2), E0M = sqrtf(e0m2);

    // thread roles for A-build
    const int r = tid >> 3, o = tid & 7;
    const int q = o >> 1, halfq = o & 1;
    const int mt = r >> 4, rr = r & 15;
    const int wsel = ((rr < 8) ? 0 : 1) + (halfq ? 2 : 0);

    // preload first tile's x into registers
    float xv[8];
    {
        const int grow = blockIdx.x * ROWS_CTA + r;
        const float* xp = x + (size_t)(grow >> 11) * (DIM * TT) + (grow & (TT - 1));
#pragma unroll
        for (int j = 0; j < 8; ++j) xv[j] = xp[(size_t)(8 * o + j) * TT];
    }
    asm volatile("cp.async.wait_group 0;" ::: "memory");
    __syncthreads();

    for (int tile = blockIdx.x; tile < NTILES; tile += gridDim.x) {
        // ---- build A from registers + per-row norms ----
        {
            uint32_t h0[4];
            float x2 = 0.f, xi2 = 0.f;
#pragma unroll
            for (int j = 0; j < 4; ++j) {
                float va = xv[2 * j], vb = xv[2 * j + 1];
                __half ha = __float2half_rn(va), hb = __float2half_rn(vb);
                float fa = __half2float(ha), fb = __half2float(hb);
                float ra = va - fa, rb = vb - fb;
                x2 += va * va + vb * vb;
                xi2 += ra * ra + rb * rb;
                h0[j] = (uint32_t)__half_as_ushort(ha) | ((uint32_t)__half_as_ushort(hb) << 16);
            }
#pragma unroll
            for (int off = 1; off < 8; off <<= 1) {
                x2  += __shfl_xor_sync(0xffffffffu, x2,  off);
                xi2 += __shfl_xor_sync(0xffffffffu, xi2, off);
            }
            if (o == 0) { sXn[r] = sqrtf(x2); sRn[r] = sqrtf(xi2); }
#pragma unroll
            for (int cc = 0; cc < 4; ++cc)
                sA[(((mt * 4 + q) * 32) + 4 * (rr & 7) + cc) * 4 + wsel] = h0[cc];
        }
        __syncthreads();

        // ---- prefetch next tile's x (consumed next iteration; hidden under MMA) ----
        float xn[8];
        {
            const int ntile = tile + gridDim.x;
            if (ntile < NTILES) {
                const int grow = ntile * ROWS_CTA + r;
                const float* xp = x + (size_t)(grow >> 11) * (DIM * TT) + (grow & (TT - 1));
#pragma unroll
                for (int j = 0; j < 8; ++j) xn[j] = xp[(size_t)(8 * o + j) * TT];
            } else {
#pragma unroll
                for (int j = 0; j < 8; ++j) xn[j] = 0.f;
            }
        }

        // ---- 8 chunks of MMA + top-2 (registers only, no syncs) ----
        float b1_[4] = {3.4e38f, 3.4e38f, 3.4e38f, 3.4e38f};
        float b2_[4] = {3.4e38f, 3.4e38f, 3.4e38f, 3.4e38f};
        int   i1_[4] = {0, 0, 0, 0};

#define UPD(h, s, c) do { \
        if ((s) < b1_[h]) { b2_[h] = b1_[h]; b1_[h] = (s); i1_[h] = (c); } \
        else if ((s) < b2_[h]) b2_[h] = (s); \
    } while (0)

        for (int ch = 0; ch < NCH; ++ch) {
            const uint32_t* Bb = (const uint32_t*)(sm + SB_OFF + ch * CHB2);
            float acc[2][2][4];
#pragma unroll
            for (int m = 0; m < 2; ++m)
#pragma unroll
                for (int n = 0; n < 2; ++n)
#pragma unroll
                    for (int j = 0; j < 4; ++j) acc[m][n][j] = 0.f;
#pragma unroll
            for (int kt = 0; kt < 4; ++kt) {
                uint4 Af[2];
#pragma unroll
                for (int m = 0; m < 2; ++m)
                    Af[m] = *(const uint4*)(sA + ((((rg * 2 + m) * 4 + kt) * 32) + lane) * 4);
#pragma unroll
                for (int n = 0; n < 2; ++n) {
                    uint2 Bf = *(const uint2*)(Bb + (((kt * 16 + cg * 2 + n) * 32) + lane) * 2);
#pragma unroll
                    for (int m = 0; m < 2; ++m) mma16816(acc[m][n], Af[m], Bf);
                }
            }
            const int cb = ch * 128 + cg * 16 + 2 * (lane & 3);
#pragma unroll
            for (int n = 0; n < 2; ++n) {
                const int c0 = cb + n * 8;
                const float ea = sE2[c0], eb = sE2[c0 + 1];
#pragma unroll
                for (int m = 0; m < 2; ++m) {
                    const int ha = 2 * m, hb = 2 * m + 1;
                    float s0 = fmaf(-2.f, acc[m][n][0], ea);
                    float s1 = fmaf(-2.f, acc[m][n][1], eb);
                    float s2 = fmaf(-2.f, acc[m][n][2], ea);
                    float s3 = fmaf(-2.f, acc[m][n][3], eb);
                    UPD(ha, s0, c0); UPD(ha, s1, c0 + 1);
                    UPD(hb, s2, c0); UPD(hb, s3, c0 + 1);
                }
            }
        }
#undef UPD

        // ---- quad merge of top-2 sets ----
#pragma unroll
        for (int h = 0; h < 4; ++h) {
#pragma unroll
            for (int off = 1; off < 4; off <<= 1) {
                float ob1 = __shfl_xor_sync(0xffffffffu, b1_[h], off);
                int   oi1 = __shfl_xor_sync(0xffffffffu, i1_[h], off);
                float ob2 = __shfl_xor_sync(0xffffffffu, b2_[h], off);
                if (ob1 < b1_[h] || (ob1 == b1_[h] && oi1 < i1_[h])) {
                    b2_[h] = fminf(b1_[h], ob2);
                    b1_[h] = ob1; i1_[h] = oi1;
                } else {
                    b2_[h] = fminf(b2_[h], ob1);
                }
            }
        }
        if ((lane & 3) == 0) {
            const int qq = lane >> 2;
#pragma unroll
            for (int h = 0; h < 4; ++h) {
                const int m = h >> 1, hb = h & 1;
                const int row = rg * 32 + m * 16 + hb * 8 + qq;
                sB1[row * 8 + cg] = b1_[h];
                sI1[row * 8 + cg] = i1_[h];
                sB2[row * 8 + cg] = b2_[h];
            }
        }
        __syncthreads();

        if (tid < ROWS_CTA) {
            float B1 = sB1[tid * 8], B2 = sB2[tid * 8];
            int   I1 = sI1[tid * 8];
#pragma unroll
            for (int g = 1; g < 8; ++g) {
                float ob1 = sB1[tid * 8 + g], ob2 = sB2[tid * 8 + g];
                int   oi1 = sI1[tid * 8 + g];
                if (ob1 < B1 || (ob1 == B1 && oi1 < I1)) {
                    B2 = fminf(B1, ob2);
                    B1 = ob1; I1 = oi1;
                } else {
                    B2 = fminf(B2, ob1);
                }
            }
            const float Wt = 4.0f * (sXn[tid] * HM + sRn[tid] * E0M) + 0.02f;
            const int grow = tile * ROWS_CTA + tid;
            if (B2 - B1 > Wt) {
                g_idx[grow] = I1;
                atomicAdd(&g_counts[I1], 1);
            } else {
                g_idx[grow] = -1;
                const int pos = atomicAdd(&g_cnt, 1);
                g_list[pos] = grow;
            }
        }
        __syncthreads();   // protect sA/sB1/sXn before next tile overwrites

#pragma unroll
        for (int j = 0; j < 8; ++j) xv[j] = xn[j];
    }
}

// ---------------- pass2: exact 2-split HMMA rescore, half-tiles (64 rows x 512 codes) ----------------
__global__ void __launch_bounds__(512, 2)
pass2_kernel(const float* __restrict__ x) {
    extern __shared__ char sm[];
    uint32_t* sA  = (uint32_t*)(sm + P2_SA);
    float*    sE2 = (float*)(sm + P2_SE2);
    float*    sRF = (float*)(sm + P2_SRF);
    int*      sRI = (int*)(sm + P2_SRI);
    int*      sL  = (int*)(sm + P2_SL);
    const uint32_t sBaddr = smem_u32(sm + P2_SB);

    const int tid = threadIdx.x, lane = tid & 31, w = tid >> 5;
    const int rg = w >> 3, cg = w & 7;
    const int cnt = g_cnt;

    for (int i = tid; i < NUM_E; i += 512) sE2[i] = g_e2[i];

    for (int ht = blockIdx.x; (ht >> 1) * 64 < cnt; ht += gridDim.x) {
        const int pair = ht >> 1, chalf = ht & 1;
        const int c0ch = chalf * 4;

        if (tid < ROWS_CTA) {
            const int p = pair * ROWS_CTA + tid;
            sL[tid] = (p < cnt) ? g_list[p] : -1;
        }
        __syncthreads();

        for (int k = tid; k < CHB / 16; k += 512)
            cp16(sBaddr + k * 16, (const char*)g_Bp + (size_t)c0ch * CHB + k * 16);
        cp_commit();
        for (int k = tid; k < CHB / 16; k += 512)
            cp16(sBaddr + CHB + k * 16, (const char*)g_Bp + (size_t)(c0ch + 1) * CHB + k * 16);
        cp_commit();

        {
            const int r = tid >> 3, o = tid & 7;
            const int q = o >> 1, halfq = o & 1;
            int grow = sL[r];
            if (grow < 0) grow = 0;
            const float* xp = x + (size_t)(grow >> 11) * (DIM * TT) + (grow & (TT - 1));
            uint32_t h0[4], h1[4];
#pragma unroll
            for (int j = 0; j < 4; ++j) {
                float va = xp[(size_t)(8 * o + 2 * j) * TT];
                float vb = xp[(size_t)(8 * o + 2 * j + 1) * TT];
                uint32_t a0, a1, b0, b1;
                split2(va, a0, a1);
                split2(vb, b0, b1);
                h0[j] = a0 | (b0 << 16);
                h1[j] = a1 | (b1 << 16);
            }
            const int mt = r >> 4, rr = r & 15;
            const int wsel = ((rr < 8) ? 0 : 1) + (halfq ? 2 : 0);
#pragma unroll
            for (int sp = 0; sp < 2; ++sp) {
                const int pkt = sp * 4 + q;
                const uint32_t* hp = sp ? h1 : h0;
#pragma unroll
                for (int cc = 0; cc < 4; ++cc)
                    sA[(((mt * 8 + pkt) * 32) + 4 * (rr & 7) + cc) * 4 + wsel] = hp[cc];
            }
        }
        __syncthreads();

        float best[4];
        int   bidx[4];
#pragma unroll
        for (int h = 0; h < 4; ++h) { best[h] = 3.4e38f; bidx[h] = 0; }

        for (int ch = 0; ch < 4; ++ch) {
            if (ch < 3) asm volatile("cp.async.wait_group 1;" ::: "memory");
            else        asm volatile("cp.async.wait_group 0;" ::: "memory");
            __syncthreads();
            const uint32_t* Bb = (const uint32_t*)(sm + P2_SB + (ch & 1) * CHB);

            float acc[2][2][4];
#pragma unroll
            for (int m = 0; m < 2; ++m)
#pragma unroll
                for (int n = 0; n < 2; ++n)
#pragma unroll
                    for (int j = 0; j < 4; ++j) acc[m][n][j] = 0.f;

#pragma unroll
            for (int lkt = 0; lkt < 8; ++lkt) {
                const int qq = lkt & 3;
                const int pa = (lkt < 4) ? qq : (4 + qq);
                const int pb = (lkt < 4) ? (4 + qq) : qq;
                uint4 Af[2];
#pragma unroll
                for (int m = 0; m < 2; ++m)
                    Af[m] = *(const uint4*)(sA + ((((rg * 2 + m) * 8 + pa) * 32) + lane) * 4);
#pragma unroll
                for (int n = 0; n < 2; ++n) {
                    uint2 Bf = *(const uint2*)(Bb + (((pb * 16 + cg * 2 + n) * 32) + lane) * 2);
#pragma unroll
                    for (int m = 0; m < 2; ++m) mma16816(acc[m][n], Af[m], Bf);
                }
            }
#pragma unroll
            for (int m = 0; m < 2; ++m)
#pragma unroll
                for (int n = 0; n < 2; ++n)
#pragma unroll
                    for (int j = 0; j < 4; ++j) acc[m][n][j] *= INV2048;
#pragma unroll
            for (int qq = 0; qq < 4; ++qq) {
                uint4 Af[2];
#pragma unroll
                for (int m = 0; m < 2; ++m)
                    Af[m] = *(const uint4*)(sA + ((((rg * 2 + m) * 8 + qq) * 32) + lane) * 4);
#pragma unroll
                for (int n = 0; n < 2; ++n) {
                    uint2 Bf = *(const uint2*)(Bb + (((qq * 16 + cg * 2 + n) * 32) + lane) * 2);
#pragma unroll
                    for (int m = 0; m < 2; ++m) mma16816(acc[m][n], Af[m], Bf);
                }
            }
            __syncthreads();

            if (ch + 2 < 4) {
                const char* src = (const char*)g_Bp + (size_t)(c0ch + ch + 2) * CHB;
                const uint32_t dst = sBaddr + (ch & 1) * CHB;
                for (int k = tid; k < CHB / 16; k += 512) cp16(dst + k * 16, src + k * 16);
                cp_commit();
            }

            const int cb = (c0ch + ch) * 128 + cg * 16 + 2 * (lane & 3);
#pragma unroll
            for (int n = 0; n < 2; ++n) {
                const int c0 = cb + n * 8;
                const float ea = sE2[c0], eb = sE2[c0 + 1];
#pragma unroll
                for (int m = 0; m < 2; ++m) {
                    const int ha = 2 * m, hb = 2 * m + 1;
                    float s0 = fmaf(-2.f, acc[m][n][0], ea);
                    float s1 = fmaf(-2.f, acc[m][n][1], eb);
                    float s2 = fmaf(-2.f, acc[m][n][2], ea);
                    float s3 = fmaf(-2.f, acc[m][n][3], eb);
                    if (s0 < best[ha]) { best[ha] = s0; bidx[ha] = c0; }
                    if (s1 < best[ha]) { best[ha] = s1; bidx[ha] = c0 + 1; }
                    if (s2 < best[hb]) { best[hb] = s2; bidx[hb] = c0; }
                    if (s3 < best[hb]) { best[hb] = s3; bidx[hb] = c0 + 1; }
                }
            }
        }

#pragma unroll
        for (int h = 0; h < 4; ++h) {
#pragma unroll
            for (int off = 1; off < 4; off <<= 1) {
                float os = __shfl_xor_sync(0xffffffffu, best[h], off);
                int   oi = __shfl_xor_sync(0xffffffffu, bidx[h], off);
                if (os < best[h] || (os == best[h] && oi < bidx[h])) { best[h] = os; bidx[h] = oi; }
            }
        }
        if ((lane & 3) == 0) {
            const int q = lane >> 2;
#pragma unroll
            for (int h = 0; h < 4; ++h) {
                const int m = h >> 1, hb = h & 1;
                const int row = rg * 32 + m * 16 + hb * 8 + q;
                sRF[row * 8 + cg] = best[h];
                sRI[row * 8 + cg] = bidx[h];
            }
        }
        __syncthreads();
        if (tid < ROWS_CTA && sL[tid] >= 0) {
            float bv = sRF[tid * 8];
            int   bi = sRI[tid * 8];
#pragma unroll
            for (int g = 1; g < 8; ++g) {
                float v = sRF[tid * 8 + g];
                int   i = sRI[tid * 8 + g];
                if (v < bv || (v == bv && i < bi)) { bv = v; bi = i; }
            }
            const unsigned long long key =
                ((unsigned long long)okey(bv) << 10) | (unsigned long long)bi;
            atomicMin(&g_slot[sL[tid]], key);
        }
        __syncthreads();
    }
}

// ---------------- gather + straight-through + losses + fused finalize ----------------
// block 512 = 64 rows x 8 dim-octants; lanes consecutive in t -> 128B coalesced
__global__ void __launch_bounds__(512)
gather_fin_kernel(const float* __restrict__ x, const float* __restrict__ embed,
                  float* __restrict__ out) {
    __shared__ float warpsum[16];
    __shared__ int s_last;
    const int tid = threadIdx.x, lane = tid & 31, w = tid >> 5;
    const int r = tid & 63, o = tid >> 6;      // 8 dims per thread
    const int row = blockIdx.x * 64 + r;
    const int b_i = row >> 11, t_i = row & (TT - 1);

    const int idx0 = g_idx[row];
    int bi = idx0;
    if (bi < 0) bi = (int)(g_slot[row] & 1023ull);
    if (o == 0) {
        out[IDX_OFF + row] = (float)bi;
        if (idx0 < 0) atomicAdd(&g_counts[bi], 1);
    }

    const float4* ep = (const float4*)(embed + (size_t)bi * DIM + o * 8);
    const float* xp = x + ((size_t)b_i * DIM + o * 8) * TT + t_i;
    float* op = out + ((size_t)b_i * DIM + o * 8) * TT + t_i;
    float s = 0.f;
#pragma unroll
    for (int j = 0; j < 2; ++j) {
        float4 e = ep[j];
        float x0 = xp[(size_t)(4 * j) * TT];
        float x1 = xp[(size_t)(4 * j + 1) * TT];
        float x2 = xp[(size_t)(4 * j + 2) * TT];
        float x3 = xp[(size_t)(4 * j + 3) * TT];
        float d0 = e.x - x0, d1 = e.y - x1, d2 = e.z - x2, d3 = e.w - x3;
        op[(size_t)(4 * j) * TT]     = x0 + d0;
        op[(size_t)(4 * j + 1) * TT] = x1 + d1;
        op[(size_t)(4 * j + 2) * TT] = x2 + d2;
        op[(size_t)(4 * j + 3) * TT] = x3 + d3;
        s += d0 * d0 + d1 * d1 + d2 * d2 + d3 * d3;
    }
#pragma unroll
    for (int off = 16; off; off >>= 1) s += __shfl_down_sync(0xffffffffu, s, off);
    if (lane == 0) warpsum[w] = s;
    __syncthreads();
    if (w == 0) {
        float v = (lane < 16) ? warpsum[lane] : 0.f;
#pragma unroll
        for (int off = 8; off; off >>= 1) v += __shfl_down_sync(0xffffffffu, v, off);
        if (lane == 0) atomicAdd(&g_sumsq, v);
    }

    if (tid == 0) {
        __threadfence();
        s_last = (atomicAdd(&g_gdone, 1) == (int)gridDim.x - 1);
    }
    __syncthreads();
    if (!s_last) return;
    __threadfence();

    {
        __shared__ float f1[16], f2[16];
        float t1 = 0.f, t2 = 0.f;
        for (int c = tid; c < NUM_E; c += 512) {
            float p = (float)g_counts[c] * (1.0f / (float)NROWS);
            out[AVG_OFF + c] = p;
            t1 += p * logf(p + 1e-10f);
            t2 += p * logf(p * (float)NUM_E + 1e-10f);
        }
#pragma unroll
        for (int off = 16; off; off >>= 1) {
            t1 += __shfl_down_sync(0xffffffffu, t1, off);
            t2 += __shfl_down_sync(0xffffffffu, t2, off);
        }
        if (lane == 0) { f1[w] = t1; f2[w] = t2; }
        __syncthreads();
        if (w == 0) {
            float a = (lane < 16) ? f1[lane] : 0.f;
            float b = (lane < 16) ? f2[lane] : 0.f;
#pragma unroll
            for (int off = 8; off; off >>= 1) {
                a += __shfl_down_sync(0xffffffffu, a, off);
                b += __shfl_down_sync(0xffffffffu, b, off);
            }
            if (lane == 0) {
                out[PERP_OFF]   = expf(-a);
                out[USAGE_OFF]  = b;
                out[COMMIT_OFF] = 0.25f * g_sumsq / (float)NELEM;
            }
        }
    }
}

extern "C" void kernel_launch(void* const* d_in, const int* in_sizes, int n_in,
                              void* d_out, int out_size) {
    const float* x     = (const float*)d_in[0];
    const float* embed = (const float*)d_in[1];
    float* out = (float*)d_out;

    cudaFuncSetAttribute(vq_mma_kernel, cudaFuncAttributeMaxDynamicSharedMemorySize, SMEM_MAIN);
    cudaFuncSetAttribute(pass2_kernel, cudaFuncAttributeMaxDynamicSharedMemorySize, SMEM_P2);

    prep_kernel<<<32, 32>>>(embed);
    vq_mma_kernel<<<148, 512, SMEM_MAIN>>>(x);
    pass2_kernel<<<296, 512, SMEM_P2>>>(x);
    gather_fin_kernel<<<NROWS / 64, 512>>>(x, embed, out);
}